// round 1
// baseline (speedup 1.0000x reference)
#include <cuda_runtime.h>
#include <cuda_bf16.h>
#include <math_constants.h>

#define N_NODES 100000
#define N_EDGES 1200000
#define N_TOT   1300000   // edges + self loops
#define D 64
#define NEG_SLOPE 0.2f
#define EPSV 1e-16f

// ---------------- device scratch (static, no allocations) ----------------
__device__ float g_hA[N_NODES * D];
__device__ float g_hB[N_NODES * D];
__device__ float g_ssrc[N_NODES];
__device__ float g_sdst[N_NODES];
__device__ float g_e[N_TOT];
__device__ int   g_deg[N_NODES];
__device__ int   g_off[N_NODES];
__device__ int   g_cur[N_NODES];
__device__ int   g_esrc[N_TOT];
__device__ int   g_bsum[128];
__device__ float g_pool[D];

// ---------------- init: deg=1 (self loop), zero pool ----------------
__global__ void k_init() {
    int i = blockIdx.x * blockDim.x + threadIdx.x;
    if (i < N_NODES) g_deg[i] = 1;
    if (i < D) g_pool[i] = 0.0f;
}

// ---------------- count incoming edges per dst ----------------
__global__ void k_count(const int* __restrict__ dst) {
    int i = blockIdx.x * blockDim.x + threadIdx.x;
    if (i < N_EDGES) atomicAdd(&g_deg[dst[i]], 1);
}

// ---------------- exclusive scan of deg -> off (3 kernels) ----------------
__global__ void k_scan1() {
    __shared__ int s[1024];
    int tid = threadIdx.x;
    int i = blockIdx.x * 1024 + tid;
    int v = (i < N_NODES) ? g_deg[i] : 0;
    s[tid] = v;
    __syncthreads();
    for (int off = 1; off < 1024; off <<= 1) {
        int t = (tid >= off) ? s[tid - off] : 0;
        __syncthreads();
        s[tid] += t;
        __syncthreads();
    }
    if (i < N_NODES) g_off[i] = s[tid] - v;   // exclusive within block
    if (tid == 1023) g_bsum[blockIdx.x] = s[1023];
}

__global__ void k_scan2(int nb) {
    if (threadIdx.x == 0) {
        int acc = 0;
        for (int i = 0; i < nb; i++) { int t = g_bsum[i]; g_bsum[i] = acc; acc += t; }
    }
}

__global__ void k_scan3() {
    int i = blockIdx.x * 1024 + threadIdx.x;
    if (i < N_NODES) {
        int v = g_off[i] + g_bsum[blockIdx.x];
        g_off[i] = v;
        g_cur[i] = v;
    }
}

// ---------------- fill CSR (edges + self loops) ----------------
__global__ void k_fill(const int* __restrict__ src, const int* __restrict__ dst) {
    int i = blockIdx.x * blockDim.x + threadIdx.x;
    if (i >= N_TOT) return;
    int s, d;
    if (i < N_EDGES) { s = src[i]; d = dst[i]; }
    else             { s = i - N_EDGES; d = s; }
    int pos = atomicAdd(&g_cur[d], 1);
    g_esrc[pos] = s;
}

// ---------------- H = X @ W  (100k x 64 @ 64 x 64) ----------------
__global__ __launch_bounds__(256) void k_gemm(const float* __restrict__ X,
                                              const float* __restrict__ W,
                                              float* __restrict__ H) {
    __shared__ __align__(16) float sW[64 * 64];
    __shared__ __align__(16) float sX[32 * 64];
    int tid = threadIdx.x;
    for (int i = tid; i < 64 * 64; i += 256) sW[i] = W[i];
    int base = blockIdx.x * 32;
    for (int i = tid; i < 32 * 64; i += 256) {
        int n = base + (i >> 6);
        sX[i] = (n < N_NODES) ? X[base * 64 + i] : 0.0f;
    }
    __syncthreads();

    int col = tid & 63;
    int ng  = tid >> 6;     // 0..3, 8 node-rows each
    float acc[8];
#pragma unroll
    for (int i = 0; i < 8; i++) acc[i] = 0.0f;

    const float4* sX4 = (const float4*)sX;
#pragma unroll
    for (int k4 = 0; k4 < 16; k4++) {
        float w0 = sW[(k4 * 4 + 0) * 64 + col];
        float w1 = sW[(k4 * 4 + 1) * 64 + col];
        float w2 = sW[(k4 * 4 + 2) * 64 + col];
        float w3 = sW[(k4 * 4 + 3) * 64 + col];
#pragma unroll
        for (int i = 0; i < 8; i++) {
            float4 xv = sX4[(ng * 8 + i) * 16 + k4];
            acc[i] += xv.x * w0 + xv.y * w1 + xv.z * w2 + xv.w * w3;
        }
    }
#pragma unroll
    for (int i = 0; i < 8; i++) {
        int n = base + ng * 8 + i;
        if (n < N_NODES) H[n * 64 + col] = acc[i];
    }
}

// ---------------- per-node attention scalars: ssrc = h.a_src, sdst = h.a_dst ---
__global__ void k_dots(const float* __restrict__ H,
                       const float* __restrict__ asrc,
                       const float* __restrict__ adst) {
    int w = (blockIdx.x * blockDim.x + threadIdx.x) >> 5;
    int lane = threadIdx.x & 31;
    if (w >= N_NODES) return;
    float2 h  = ((const float2*)H)[w * 32 + lane];
    float2 as = ((const float2*)asrc)[lane];
    float2 ad = ((const float2*)adst)[lane];
    float p = h.x * as.x + h.y * as.y;
    float q = h.x * ad.x + h.y * ad.y;
#pragma unroll
    for (int o = 16; o > 0; o >>= 1) {
        p += __shfl_xor_sync(0xffffffffu, p, o);
        q += __shfl_xor_sync(0xffffffffu, q, o);
    }
    if (lane == 0) { g_ssrc[w] = p; g_sdst[w] = q; }
}

// ---------------- warp-per-dst-node softmax + aggregation ----------------
__global__ __launch_bounds__(256) void k_attn(const float* __restrict__ H,
                                              const float* __restrict__ b,
                                              float* __restrict__ OUT) {
    int node = (blockIdx.x * blockDim.x + threadIdx.x) >> 5;
    int lane = threadIdx.x & 31;
    if (node >= N_NODES) return;

    int off = g_off[node];
    int deg = g_deg[node];
    float sd = g_sdst[node];

    // pass 1: e = leaky_relu(ssrc[src]+sdst[dst]), running max
    float mx = -CUDART_INF_F;
    for (int j = lane; j < deg; j += 32) {
        int s = g_esrc[off + j];
        float e = g_ssrc[s] + sd;
        e = (e > 0.0f) ? e : NEG_SLOPE * e;
        g_e[off + j] = e;
        mx = fmaxf(mx, e);
    }
#pragma unroll
    for (int o = 16; o > 0; o >>= 1) mx = fmaxf(mx, __shfl_xor_sync(0xffffffffu, mx, o));

    // pass 2: ex = exp(e - mx), sum
    float sum = 0.0f;
    for (int j = lane; j < deg; j += 32) {
        float ex = __expf(g_e[off + j] - mx);
        g_e[off + j] = ex;
        sum += ex;
    }
#pragma unroll
    for (int o = 16; o > 0; o >>= 1) sum += __shfl_xor_sync(0xffffffffu, sum, o);
    float inv = 1.0f / (sum + EPSV);

    __threadfence_block();
    __syncwarp();

    // pass 3: out = sum_j alpha_j * h[src_j]; each lane owns 2 dims
    float a0 = 0.0f, a1 = 0.0f;
    for (int j = 0; j < deg; j++) {
        int s = g_esrc[off + j];        // broadcast
        float ex = g_e[off + j];        // broadcast
        float2 hv = ((const float2*)H)[s * 32 + lane];
        a0 += ex * hv.x;
        a1 += ex * hv.y;
    }
    float2 bb = ((const float2*)b)[lane];
    float r0 = a0 * inv + bb.x;
    float r1 = a1 * inv + bb.y;
    r0 = fmaxf(r0, 0.0f);   // relu (applied after both GAT layers)
    r1 = fmaxf(r1, 0.0f);
    float2 rv; rv.x = r0; rv.y = r1;
    ((float2*)OUT)[node * 32 + lane] = rv;
}

// ---------------- column-wise mean pool (accumulate sums into g_pool) -------
__global__ void k_pool(const float* __restrict__ H) {
    int gw = (blockIdx.x * blockDim.x + threadIdx.x) >> 5;
    int lane = threadIdx.x & 31;
    int nw = (gridDim.x * blockDim.x) >> 5;
    float a0 = 0.0f, a1 = 0.0f;
    for (int n = gw; n < N_NODES; n += nw) {
        float2 h = ((const float2*)H)[n * 32 + lane];
        a0 += h.x;
        a1 += h.y;
    }
    atomicAdd(&g_pool[lane * 2], a0);
    atomicAdd(&g_pool[lane * 2 + 1], a1);
}

// ---------------- final: out = (pool/N) . W_out + b_out ----------------
__global__ void k_final(const float* __restrict__ Wout,
                        const float* __restrict__ bout,
                        float* __restrict__ out) {
    __shared__ float s[2];
    int t = threadIdx.x;      // 64 threads
    float v = (g_pool[t] * (1.0f / (float)N_NODES)) * Wout[t];
#pragma unroll
    for (int o = 16; o > 0; o >>= 1) v += __shfl_xor_sync(0xffffffffu, v, o);
    if ((t & 31) == 0) s[t >> 5] = v;
    __syncthreads();
    if (t == 0) out[0] = s[0] + s[1] + bout[0];
}

// ---------------- launcher ----------------
extern "C" void kernel_launch(void* const* d_in, const int* in_sizes, int n_in,
                              void* d_out, int out_size) {
    const float* x      = (const float*)d_in[0];
    const int*   eidx   = (const int*)d_in[1];
    const float* W1     = (const float*)d_in[2];
    const float* a_src1 = (const float*)d_in[3];
    const float* a_dst1 = (const float*)d_in[4];
    const float* b1     = (const float*)d_in[5];
    const float* W2     = (const float*)d_in[6];
    const float* a_src2 = (const float*)d_in[7];
    const float* a_dst2 = (const float*)d_in[8];
    const float* b2     = (const float*)d_in[9];
    const float* W_out  = (const float*)d_in[10];
    const float* b_out  = (const float*)d_in[11];
    float* out = (float*)d_out;

    const int* src = eidx;
    const int* dst = eidx + N_EDGES;

    float* hA; cudaGetSymbolAddress((void**)&hA, g_hA);
    float* hB; cudaGetSymbolAddress((void**)&hB, g_hB);

    int nbScan = (N_NODES + 1023) / 1024;   // 98

    k_init<<<(N_NODES + 255) / 256, 256>>>();
    k_count<<<(N_EDGES + 255) / 256, 256>>>(dst);
    k_scan1<<<nbScan, 1024>>>();
    k_scan2<<<1, 32>>>(nbScan);
    k_scan3<<<nbScan, 1024>>>();
    k_fill<<<(N_TOT + 255) / 256, 256>>>(src, dst);

    // layer 1: x -> hA -> hB
    k_gemm<<<(N_NODES + 31) / 32, 256>>>(x, W1, hA);
    k_dots<<<(N_NODES * 32 + 255) / 256, 256>>>(hA, a_src1, a_dst1);
    k_attn<<<(N_NODES * 32 + 255) / 256, 256>>>(hA, b1, hB);

    // layer 2: hB -> hA -> hB
    k_gemm<<<(N_NODES + 31) / 32, 256>>>(hB, W2, hA);
    k_dots<<<(N_NODES * 32 + 255) / 256, 256>>>(hA, a_src2, a_dst2);
    k_attn<<<(N_NODES * 32 + 255) / 256, 256>>>(hA, b2, hB);

    // pool + output
    k_pool<<<148, 256>>>(hB);
    k_final<<<1, 64>>>(W_out, b_out, out);
}

// round 5
// speedup vs baseline: 1.1629x; 1.1629x over previous
#include <cuda_runtime.h>
#include <cuda_bf16.h>
#include <math_constants.h>

#define N_NODES 100000
#define N_EDGES 1200000
#define N_TOT   1300000   // edges + self loops
#define D 64
#define NEG_SLOPE 0.2f
#define EPSV 1e-16f
#define TM 128            // gemm rows per block

// ---------------- device scratch (static, no allocations) ----------------
__device__ float g_hA[N_NODES * D];
__device__ float g_hB[N_NODES * D];
__device__ float g_ssrc[N_NODES];
__device__ float g_sdst[N_NODES];
__device__ int   g_deg[N_NODES];
__device__ int   g_off[N_NODES];
__device__ int   g_cur[N_NODES];
__device__ int   g_esrc[N_TOT];
__device__ int   g_bsum[128];
__device__ float g_pool[D];

// ---------------- init: deg=1 (self loop), zero pool ----------------
__global__ void k_init() {
    int i = blockIdx.x * blockDim.x + threadIdx.x;
    if (i < N_NODES) g_deg[i] = 1;
    if (i < D) g_pool[i] = 0.0f;
}

// ---------------- count incoming edges per dst ----------------
__global__ void k_count(const int* __restrict__ dst) {
    int i = blockIdx.x * blockDim.x + threadIdx.x;
    if (i < N_EDGES) atomicAdd(&g_deg[dst[i]], 1);
}

// ---------------- exclusive scan of deg -> off ----------------
__global__ void k_scan1() {
    __shared__ int s[1024];
    int tid = threadIdx.x;
    int i = blockIdx.x * 1024 + tid;
    int v = (i < N_NODES) ? g_deg[i] : 0;
    s[tid] = v;
    __syncthreads();
    for (int off = 1; off < 1024; off <<= 1) {
        int t = (tid >= off) ? s[tid - off] : 0;
        __syncthreads();
        s[tid] += t;
        __syncthreads();
    }
    if (i < N_NODES) g_off[i] = s[tid] - v;   // exclusive within block
    if (tid == 1023) g_bsum[blockIdx.x] = s[1023];
}

// parallel scan of the 98 block sums (single block, 128 threads)
__global__ void k_scan2() {
    __shared__ int s[128];
    int t = threadIdx.x;
    int v = (t < 98) ? g_bsum[t] : 0;
    s[t] = v;
    __syncthreads();
    for (int off = 1; off < 128; off <<= 1) {
        int u = (t >= off) ? s[t - off] : 0;
        __syncthreads();
        s[t] += u;
        __syncthreads();
    }
    if (t < 98) g_bsum[t] = s[t] - v;         // exclusive
}

__global__ void k_scan3() {
    int i = blockIdx.x * 1024 + threadIdx.x;
    if (i < N_NODES) {
        int v = g_off[i] + g_bsum[blockIdx.x];
        g_off[i] = v;
        g_cur[i] = v;
    }
}

// ---------------- fill CSR (edges + self loops) ----------------
__global__ void k_fill(const int* __restrict__ src, const int* __restrict__ dst) {
    int i = blockIdx.x * blockDim.x + threadIdx.x;
    if (i >= N_TOT) return;
    int s, d;
    if (i < N_EDGES) { s = src[i]; d = dst[i]; }
    else             { s = i - N_EDGES; d = s; }
    int pos = atomicAdd(&g_cur[d], 1);
    g_esrc[pos] = s;
}

// ---------------- H = X @ W (100k x 64 @ 64 x 64), 8x4 register tile ------
// 256 threads, 128 rows/block. Per k4-iter per thread: 192B LDS / 128 FMA
// = 1.5 B/FMA < 2 B/FMA crossbar bound -> FFMA-bound.
// Epilogue also computes ssrc = h.a_src, sdst = h.a_dst per row (fused dots):
// threads rg*16..rg*16+15 (one 16-lane half-warp) hold all 64 cols of the
// row group, so a 4-step shfl_xor butterfly (1,2,4,8) reduces within it.
__global__ __launch_bounds__(256, 2) void k_gemm(const float* __restrict__ X,
                                                 const float* __restrict__ W,
                                                 const float* __restrict__ asrc,
                                                 const float* __restrict__ adst,
                                                 float* __restrict__ H) {
    __shared__ __align__(16) float4 sW[64 * 16];   // [k][colgroup]
    __shared__ __align__(16) float4 sX[TM * 16];   // [row][k4]
    int tid = threadIdx.x;
    const float4* W4 = (const float4*)W;
    for (int i = tid; i < 64 * 16; i += 256) sW[i] = W4[i];

    int base = blockIdx.x * TM;
    const float4* X4 = (const float4*)X;
    for (int i = tid; i < TM * 16; i += 256) {
        int row = base + (i >> 4);
        sX[i] = (row < N_NODES) ? X4[(size_t)base * 16 + i]
                                : make_float4(0.f, 0.f, 0.f, 0.f);
    }
    __syncthreads();

    int cg = tid & 15;    // col group: cols 4*cg..4*cg+3
    int rg = tid >> 4;    // row group: rows 8*rg..8*rg+7
    float acc[8][4];
#pragma unroll
    for (int r = 0; r < 8; r++)
#pragma unroll
        for (int c = 0; c < 4; c++) acc[r][c] = 0.0f;

#pragma unroll
    for (int k4 = 0; k4 < 16; k4++) {
        float4 w0 = sW[(k4 * 4 + 0) * 16 + cg];
        float4 w1 = sW[(k4 * 4 + 1) * 16 + cg];
        float4 w2 = sW[(k4 * 4 + 2) * 16 + cg];
        float4 w3 = sW[(k4 * 4 + 3) * 16 + cg];
#pragma unroll
        for (int r = 0; r < 8; r++) {
            float4 xv = sX[(rg * 8 + r) * 16 + k4];
            acc[r][0] += xv.x * w0.x + xv.y * w1.x + xv.z * w2.x + xv.w * w3.x;
            acc[r][1] += xv.x * w0.y + xv.y * w1.y + xv.z * w2.y + xv.w * w3.y;
            acc[r][2] += xv.x * w0.z + xv.y * w1.z + xv.z * w2.z + xv.w * w3.z;
            acc[r][3] += xv.x * w0.w + xv.y * w1.w + xv.z * w2.w + xv.w * w3.w;
        }
    }

    // write H tile
#pragma unroll
    for (int r = 0; r < 8; r++) {
        int row = base + rg * 8 + r;
        if (row < N_NODES)
            ((float4*)H)[(size_t)row * 16 + cg] =
                make_float4(acc[r][0], acc[r][1], acc[r][2], acc[r][3]);
    }

    // fused attention dots
    float4 av = ((const float4*)asrc)[cg];
    float4 dv = ((const float4*)adst)[cg];
    int lane = tid & 31;
#pragma unroll
    for (int r = 0; r < 8; r++) {
        float p = acc[r][0] * av.x + acc[r][1] * av.y +
                  acc[r][2] * av.z + acc[r][3] * av.w;
        float q = acc[r][0] * dv.x + acc[r][1] * dv.y +
                  acc[r][2] * dv.z + acc[r][3] * dv.w;
#pragma unroll
        for (int o = 8; o > 0; o >>= 1) {
            p += __shfl_xor_sync(0xffffffffu, p, o);
            q += __shfl_xor_sync(0xffffffffu, q, o);
        }
        if ((lane & 15) == 0) {
            int row = base + rg * 8 + r;
            if (row < N_NODES) { g_ssrc[row] = p; g_sdst[row] = q; }
        }
    }
}

// ---------------- fused single-pass softmax + aggregation ----------------
// One warp per dst node. No max subtraction (e ~ O(10) max; exp safe in fp32,
// ratios identical). Accumulate numerator and denominator together.
// DO_POOL: skip writing OUT; block-reduce relu(result) into g_pool instead.
template <bool DO_POOL>
__global__ __launch_bounds__(256) void k_attn(const float* __restrict__ H,
                                              const float* __restrict__ b,
                                              float* __restrict__ OUT) {
    __shared__ float sp[64];
    if (DO_POOL) {
        if (threadIdx.x < 64) sp[threadIdx.x] = 0.0f;
        __syncthreads();
    }

    int node = (blockIdx.x * blockDim.x + threadIdx.x) >> 5;  // always < N_NODES
    int lane = threadIdx.x & 31;

    int off = g_off[node];
    int deg = g_deg[node];
    float sd = g_sdst[node];

    float ax = 0.0f, ay = 0.0f, se = 0.0f;
    for (int jb = 0; jb < deg; jb += 32) {
        int j = jb + lane;
        int s = 0; float ex = 0.0f;
        if (j < deg) {
            s = g_esrc[off + j];
            float e = g_ssrc[s] + sd;
            e = (e > 0.0f) ? e : NEG_SLOPE * e;
            ex = __expf(e);
        }
        se += ex;
        int cnt = min(32, deg - jb);
        for (int k = 0; k < cnt; k++) {
            int   ss  = __shfl_sync(0xffffffffu, s, k);
            float exk = __shfl_sync(0xffffffffu, ex, k);
            float2 hv = ((const float2*)H)[(size_t)ss * 32 + lane];
            ax += exk * hv.x;
            ay += exk * hv.y;
        }
    }
#pragma unroll
    for (int o = 16; o > 0; o >>= 1) se += __shfl_xor_sync(0xffffffffu, se, o);
    float inv = 1.0f / (se + EPSV);

    float2 bb = ((const float2*)b)[lane];
    float r0 = fmaxf(ax * inv + bb.x, 0.0f);
    float r1 = fmaxf(ay * inv + bb.y, 0.0f);

    if (!DO_POOL) {
        float2 rv; rv.x = r0; rv.y = r1;
        ((float2*)OUT)[(size_t)node * 32 + lane] = rv;
    } else {
        atomicAdd(&sp[lane * 2],     r0);
        atomicAdd(&sp[lane * 2 + 1], r1);
        __syncthreads();
        if (threadIdx.x < 64) atomicAdd(&g_pool[threadIdx.x], sp[threadIdx.x]);
    }
}

// ---------------- final: out = (pool/N) . W_out + b_out ----------------
__global__ void k_final(const float* __restrict__ Wout,
                        const float* __restrict__ bout,
                        float* __restrict__ out) {
    __shared__ float s[2];
    int t = threadIdx.x;      // 64 threads
    float v = (g_pool[t] * (1.0f / (float)N_NODES)) * Wout[t];
#pragma unroll
    for (int o = 16; o > 0; o >>= 1) v += __shfl_xor_sync(0xffffffffu, v, o);
    if ((t & 31) == 0) s[t >> 5] = v;
    __syncthreads();
    if (t == 0) out[0] = s[0] + s[1] + bout[0];
}

// ---------------- launcher ----------------
extern "C" void kernel_launch(void* const* d_in, const int* in_sizes, int n_in,
                              void* d_out, int out_size) {
    const float* x      = (const float*)d_in[0];
    const int*   eidx   = (const int*)d_in[1];
    const float* W1     = (const float*)d_in[2];
    const float* a_src1 = (const float*)d_in[3];
    const float* a_dst1 = (const float*)d_in[4];
    const float* b1     = (const float*)d_in[5];
    const float* W2     = (const float*)d_in[6];
    const float* a_src2 = (const float*)d_in[7];
    const float* a_dst2 = (const float*)d_in[8];
    const float* b2     = (const float*)d_in[9];
    const float* W_out  = (const float*)d_in[10];
    const float* b_out  = (const float*)d_in[11];
    float* out = (float*)d_out;

    const int* src = eidx;
    const int* dst = eidx + N_EDGES;

    float* hA; cudaGetSymbolAddress((void**)&hA, g_hA);
    float* hB; cudaGetSymbolAddress((void**)&hB, g_hB);

    int nbScan = (N_NODES + 1023) / 1024;   // 98
    int nbGemm = (N_NODES + TM - 1) / TM;   // 782
    int nbWarp = (N_NODES * 32) / 256;      // 12500 (exact)

    k_init<<<(N_NODES + 255) / 256, 256>>>();
    k_count<<<(N_EDGES + 255) / 256, 256>>>(dst);
    k_scan1<<<nbScan, 1024>>>();
    k_scan2<<<1, 128>>>();
    k_scan3<<<nbScan, 1024>>>();
    k_fill<<<(N_TOT + 255) / 256, 256>>>(src, dst);

    // layer 1: x -> hA -> hB   (gemm also emits ssrc/sdst)
    k_gemm<<<nbGemm, 256>>>(x, W1, a_src1, a_dst1, hA);
    k_attn<false><<<nbWarp, 256>>>(hA, b1, hB);

    // layer 2: hB -> hA -> (pool)
    k_gemm<<<nbGemm, 256>>>(hB, W2, a_src2, a_dst2, hA);
    k_attn<true><<<nbWarp, 256>>>(hA, b2, nullptr);

    k_final<<<1, 64>>>(W_out, b_out, out);
}

// round 7
// speedup vs baseline: 1.2865x; 1.1063x over previous
#include <cuda_runtime.h>
#include <cuda_bf16.h>
#include <math_constants.h>

#define N_NODES 100000
#define N_EDGES 1200000
#define N_TOT   1300000   // edges + self loops
#define D 64
#define NEG_SLOPE 0.2f
#define EPSV 1e-16f
#define TM 128            // gemm rows per block

// ---------------- device scratch (static, no allocations) ----------------
__device__ float g_hA[N_NODES * D];
__device__ float g_hB[N_NODES * D];
__device__ float g_ssrc[N_NODES];
__device__ float g_sdst[N_NODES];
__device__ int   g_deg[N_NODES];
__device__ int   g_off[N_NODES];
__device__ int   g_cur[N_NODES];
__device__ int   g_esrc[N_TOT];
__device__ int   g_bsum[128];
__device__ float g_pool[D];

// ---------------- count incoming edges per dst (incl. self loops) ---------
__global__ void k_count(const int* __restrict__ dst) {
    int i = blockIdx.x * blockDim.x + threadIdx.x;
    if (i < N_EDGES) atomicAdd(&g_deg[dst[i]], 1);
    if (i < N_NODES) atomicAdd(&g_deg[i], 1);   // self loop
}

// ---------------- exclusive scan of deg -> off ----------------
__global__ void k_scan1() {
    __shared__ int s[1024];
    int tid = threadIdx.x;
    int i = blockIdx.x * 1024 + tid;
    int v = (i < N_NODES) ? g_deg[i] : 0;
    s[tid] = v;
    __syncthreads();
    for (int off = 1; off < 1024; off <<= 1) {
        int t = (tid >= off) ? s[tid - off] : 0;
        __syncthreads();
        s[tid] += t;
        __syncthreads();
    }
    if (i < N_NODES) g_off[i] = s[tid] - v;   // exclusive within block
    if (tid == 1023) g_bsum[blockIdx.x] = s[1023];
}

// parallel scan of the 98 block sums (single block, 128 threads)
__global__ void k_scan2() {
    __shared__ int s[128];
    int t = threadIdx.x;
    int v = (t < 98) ? g_bsum[t] : 0;
    s[t] = v;
    __syncthreads();
    for (int off = 1; off < 128; off <<= 1) {
        int u = (t >= off) ? s[t - off] : 0;
        __syncthreads();
        s[t] += u;
        __syncthreads();
    }
    if (t < 98) g_bsum[t] = s[t] - v;         // exclusive
}

__global__ void k_scan3() {
    int i = blockIdx.x * 1024 + threadIdx.x;
    if (i < N_NODES) {
        int v = g_off[i] + g_bsum[blockIdx.x];
        g_off[i] = v;
        g_cur[i] = v;
    }
}

// ---------------- fill CSR (edges + self loops) ----------------
__global__ void k_fill(const int* __restrict__ src, const int* __restrict__ dst) {
    int i = blockIdx.x * blockDim.x + threadIdx.x;
    if (i >= N_TOT) return;
    int s, d;
    if (i < N_EDGES) { s = src[i]; d = dst[i]; }
    else             { s = i - N_EDGES; d = s; }
    int pos = atomicAdd(&g_cur[d], 1);
    g_esrc[pos] = s;
}

// ---------------- H = X @ W (100k x 64 @ 64 x 64), 8x4 register tile ------
// Epilogue also computes ssrc = h.a_src, sdst = h.a_dst per row (fused dots).
__global__ __launch_bounds__(256, 2) void k_gemm(const float* __restrict__ X,
                                                 const float* __restrict__ W,
                                                 const float* __restrict__ asrc,
                                                 const float* __restrict__ adst,
                                                 float* __restrict__ H) {
    __shared__ __align__(16) float4 sW[64 * 16];   // [k][colgroup]
    __shared__ __align__(16) float4 sX[TM * 16];   // [row][k4]
    int tid = threadIdx.x;
    const float4* W4 = (const float4*)W;
    for (int i = tid; i < 64 * 16; i += 256) sW[i] = W4[i];

    int base = blockIdx.x * TM;
    const float4* X4 = (const float4*)X;
    for (int i = tid; i < TM * 16; i += 256) {
        int row = base + (i >> 4);
        sX[i] = (row < N_NODES) ? X4[(size_t)base * 16 + i]
                                : make_float4(0.f, 0.f, 0.f, 0.f);
    }
    __syncthreads();

    int cg = tid & 15;    // col group: cols 4*cg..4*cg+3
    int rg = tid >> 4;    // row group: rows 8*rg..8*rg+7
    float acc[8][4];
#pragma unroll
    for (int r = 0; r < 8; r++)
#pragma unroll
        for (int c = 0; c < 4; c++) acc[r][c] = 0.0f;

#pragma unroll
    for (int k4 = 0; k4 < 16; k4++) {
        float4 w0 = sW[(k4 * 4 + 0) * 16 + cg];
        float4 w1 = sW[(k4 * 4 + 1) * 16 + cg];
        float4 w2 = sW[(k4 * 4 + 2) * 16 + cg];
        float4 w3 = sW[(k4 * 4 + 3) * 16 + cg];
#pragma unroll
        for (int r = 0; r < 8; r++) {
            float4 xv = sX[(rg * 8 + r) * 16 + k4];
            acc[r][0] += xv.x * w0.x + xv.y * w1.x + xv.z * w2.x + xv.w * w3.x;
            acc[r][1] += xv.x * w0.y + xv.y * w1.y + xv.z * w2.y + xv.w * w3.y;
            acc[r][2] += xv.x * w0.z + xv.y * w1.z + xv.z * w2.z + xv.w * w3.z;
            acc[r][3] += xv.x * w0.w + xv.y * w1.w + xv.z * w2.w + xv.w * w3.w;
        }
    }

    // write H tile
#pragma unroll
    for (int r = 0; r < 8; r++) {
        int row = base + rg * 8 + r;
        if (row < N_NODES)
            ((float4*)H)[(size_t)row * 16 + cg] =
                make_float4(acc[r][0], acc[r][1], acc[r][2], acc[r][3]);
    }

    // fused attention dots: reduce over the 16 lanes of each half-warp
    float4 av = ((const float4*)asrc)[cg];
    float4 dv = ((const float4*)adst)[cg];
    int lane = tid & 31;
#pragma unroll
    for (int r = 0; r < 8; r++) {
        float p = acc[r][0] * av.x + acc[r][1] * av.y +
                  acc[r][2] * av.z + acc[r][3] * av.w;
        float q = acc[r][0] * dv.x + acc[r][1] * dv.y +
                  acc[r][2] * dv.z + acc[r][3] * dv.w;
#pragma unroll
        for (int o = 8; o > 0; o >>= 1) {
            p += __shfl_xor_sync(0xffffffffu, p, o);
            q += __shfl_xor_sync(0xffffffffu, q, o);
        }
        if ((lane & 15) == 0) {
            int row = base + rg * 8 + r;
            if (row < N_NODES) { g_ssrc[row] = p; g_sdst[row] = q; }
        }
    }
}

// ---------------- fused single-pass softmax + aggregation ----------------
// One warp per dst node. Inner broadcast loop unrolled x4 so 4 independent
// h[src] gathers are in flight per warp (MLP 4) instead of 1.
template <bool DO_POOL>
__global__ __launch_bounds__(256) void k_attn(const float* __restrict__ H,
                                              const float* __restrict__ b,
                                              float* __restrict__ OUT) {
    __shared__ float sp[64];
    if (DO_POOL) {
        if (threadIdx.x < 64) sp[threadIdx.x] = 0.0f;
        __syncthreads();
    }

    int node = (blockIdx.x * blockDim.x + threadIdx.x) >> 5;  // always < N_NODES
    int lane = threadIdx.x & 31;

    int off = g_off[node];
    int deg = g_deg[node];
    float sd = g_sdst[node];
    const float2* H2 = (const float2*)H;

    float ax = 0.0f, ay = 0.0f, se = 0.0f;
    for (int jb = 0; jb < deg; jb += 32) {
        int j = jb + lane;
        int s = 0; float ex = 0.0f;
        if (j < deg) {
            s = g_esrc[off + j];
            float e = g_ssrc[s] + sd;
            e = (e > 0.0f) ? e : NEG_SLOPE * e;
            ex = __expf(e);
        }
        se += ex;
        int cnt = min(32, deg - jb);
        int k = 0;
        for (; k + 4 <= cnt; k += 4) {
            int   s0 = __shfl_sync(0xffffffffu, s, k);
            int   s1 = __shfl_sync(0xffffffffu, s, k + 1);
            int   s2 = __shfl_sync(0xffffffffu, s, k + 2);
            int   s3 = __shfl_sync(0xffffffffu, s, k + 3);
            float e0 = __shfl_sync(0xffffffffu, ex, k);
            float e1 = __shfl_sync(0xffffffffu, ex, k + 1);
            float e2 = __shfl_sync(0xffffffffu, ex, k + 2);
            float e3 = __shfl_sync(0xffffffffu, ex, k + 3);
            float2 h0 = H2[(size_t)s0 * 32 + lane];
            float2 h1 = H2[(size_t)s1 * 32 + lane];
            float2 h2 = H2[(size_t)s2 * 32 + lane];
            float2 h3 = H2[(size_t)s3 * 32 + lane];
            ax += e0 * h0.x; ay += e0 * h0.y;
            ax += e1 * h1.x; ay += e1 * h1.y;
            ax += e2 * h2.x; ay += e2 * h2.y;
            ax += e3 * h3.x; ay += e3 * h3.y;
        }
        for (; k < cnt; k++) {
            int   ss  = __shfl_sync(0xffffffffu, s, k);
            float exk = __shfl_sync(0xffffffffu, ex, k);
            float2 hv = H2[(size_t)ss * 32 + lane];
            ax += exk * hv.x;
            ay += exk * hv.y;
        }
    }
#pragma unroll
    for (int o = 16; o > 0; o >>= 1) se += __shfl_xor_sync(0xffffffffu, se, o);
    float inv = 1.0f / (se + EPSV);

    float2 bb = ((const float2*)b)[lane];
    float r0 = fmaxf(ax * inv + bb.x, 0.0f);
    float r1 = fmaxf(ay * inv + bb.y, 0.0f);

    if (!DO_POOL) {
        float2 rv; rv.x = r0; rv.y = r1;
        ((float2*)OUT)[(size_t)node * 32 + lane] = rv;
    } else {
        atomicAdd(&sp[lane * 2],     r0);
        atomicAdd(&sp[lane * 2 + 1], r1);
        __syncthreads();
        if (threadIdx.x < 64) atomicAdd(&g_pool[threadIdx.x], sp[threadIdx.x]);
    }
}

// ---------------- final: out = (pool/N) . W_out + b_out ----------------
__global__ void k_final(const float* __restrict__ Wout,
                        const float* __restrict__ bout,
                        float* __restrict__ out) {
    __shared__ float s[2];
    int t = threadIdx.x;      // 64 threads
    float v = (g_pool[t] * (1.0f / (float)N_NODES)) * Wout[t];
#pragma unroll
    for (int o = 16; o > 0; o >>= 1) v += __shfl_xor_sync(0xffffffffu, v, o);
    if ((t & 31) == 0) s[t >> 5] = v;
    __syncthreads();
    if (t == 0) out[0] = s[0] + s[1] + bout[0];
}

// ---------------- launcher ----------------
extern "C" void kernel_launch(void* const* d_in, const int* in_sizes, int n_in,
                              void* d_out, int out_size) {
    const float* x      = (const float*)d_in[0];
    const int*   eidx   = (const int*)d_in[1];
    const float* W1     = (const float*)d_in[2];
    const float* a_src1 = (const float*)d_in[3];
    const float* a_dst1 = (const float*)d_in[4];
    const float* b1     = (const float*)d_in[5];
    const float* W2     = (const float*)d_in[6];
    const float* a_src2 = (const float*)d_in[7];
    const float* a_dst2 = (const float*)d_in[8];
    const float* b2     = (const float*)d_in[9];
    const float* W_out  = (const float*)d_in[10];
    const float* b_out  = (const float*)d_in[11];
    float* out = (float*)d_out;

    const int* src = eidx;
    const int* dst = eidx + N_EDGES;

    float* hA;   cudaGetSymbolAddress((void**)&hA, g_hA);
    float* hB;   cudaGetSymbolAddress((void**)&hB, g_hB);
    int*   degp; cudaGetSymbolAddress((void**)&degp, g_deg);
    float* poolp; cudaGetSymbolAddress((void**)&poolp, g_pool);

    // persistent secondary stream + events (host objects, created once; no
    // device memory involved). Used to fork gemm1 parallel to the CSR build
    // inside the captured graph.
    static cudaStream_t sB = nullptr;
    static cudaEvent_t evFork = nullptr, evJoin = nullptr;
    if (sB == nullptr) {
        cudaStreamCreateWithFlags(&sB, cudaStreamNonBlocking);
        cudaEventCreateWithFlags(&evFork, cudaEventDisableTiming);
        cudaEventCreateWithFlags(&evJoin, cudaEventDisableTiming);
    }

    int nbScan = (N_NODES + 1023) / 1024;   // 98
    int nbGemm = (N_NODES + TM - 1) / TM;   // 782
    int nbWarp = (N_NODES * 32) / 256;      // 12500 (exact)

    // ---- fork: gemm1 on sB, CSR build on the main (capture) stream ----
    cudaEventRecord(evFork, 0);
    cudaStreamWaitEvent(sB, evFork, 0);
    k_gemm<<<nbGemm, 256, 0, sB>>>(x, W1, a_src1, a_dst1, hA);
    cudaEventRecord(evJoin, sB);

    cudaMemsetAsync(degp, 0, N_NODES * sizeof(int), 0);
    cudaMemsetAsync(poolp, 0, D * sizeof(float), 0);
    k_count<<<(N_EDGES + 255) / 256, 256>>>(dst);
    k_scan1<<<nbScan, 1024>>>();
    k_scan2<<<1, 128>>>();
    k_scan3<<<nbScan, 1024>>>();
    k_fill<<<(N_TOT + 255) / 256, 256>>>(src, dst);

    // ---- join: attn1 needs both CSR and gemm1 results ----
    cudaStreamWaitEvent(0, evJoin, 0);
    k_attn<false><<<nbWarp, 256>>>(hA, b1, hB);

    // layer 2: hB -> hA -> (pool)
    k_gemm<<<nbGemm, 256>>>(hB, W2, a_src2, a_dst2, hA);
    k_attn<true><<<nbWarp, 256>>>(hA, b2, nullptr);

    k_final<<<1, 64>>>(W_out, b_out, out);
}

// round 8
// speedup vs baseline: 1.3574x; 1.0551x over previous
#include <cuda_runtime.h>
#include <cuda_bf16.h>
#include <math_constants.h>

#define N_NODES 100000
#define N_EDGES 1200000
#define N_TOT   1300000   // edges + self loops
#define D 64
#define NEG_SLOPE 0.2f
#define EPSV 1e-16f
#define TM 128            // gemm rows per block
#define NB_SCAN 98        // ceil(N_NODES/1024)

// ---------------- device scratch (static, no allocations) ----------------
__device__ __nv_bfloat16 g_hA[N_NODES * D];   // gathered operand, bf16
__device__ float g_hB[N_NODES * D];           // attn1 output (gemm2 input), fp32
__device__ float g_ssrc[N_NODES];
__device__ float g_sdst[N_NODES];
__device__ int   g_deg[N_NODES];
__device__ int   g_off[N_NODES];
__device__ int   g_cur[N_NODES];
__device__ int   g_esrc[N_TOT];
__device__ unsigned long long g_desc[128];    // decoupled-lookback descriptors
__device__ float g_pool[D];

// ---------------- count incoming edges per dst (incl. self loops) ---------
// Also resets the scan descriptors (runs before k_scanall in stream order).
__global__ void k_count(const int* __restrict__ dst) {
    int i = blockIdx.x * blockDim.x + threadIdx.x;
    if (i < 128) g_desc[i] = 0ULL;
    if (i < N_EDGES) atomicAdd(&g_deg[dst[i]], 1);
    if (i < N_NODES) atomicAdd(&g_deg[i], 1);   // self loop
}

// ---------------- single-kernel exclusive scan (decoupled lookback) -------
// 98 blocks x 1024 threads, all resident in one wave (98 < 148 SMs), so the
// spin on predecessor descriptors cannot deadlock. Descriptor packs
// (value<<2)|state, state: 0=invalid, 1=aggregate, 2=inclusive-prefix.
__global__ void k_scanall() {
    __shared__ int s[1024];
    __shared__ int s_pref;
    int tid = threadIdx.x, b = blockIdx.x;
    int i = b * 1024 + tid;
    int v = (i < N_NODES) ? g_deg[i] : 0;
    s[tid] = v;
    __syncthreads();
    for (int off = 1; off < 1024; off <<= 1) {
        int t = (tid >= off) ? s[tid - off] : 0;
        __syncthreads();
        s[tid] += t;
        __syncthreads();
    }
    int agg = s[1023];
    if (tid == 0) {
        long long epref = 0;
        if (b == 0) {
            atomicExch(&g_desc[0], ((unsigned long long)agg << 2) | 2ULL);
        } else {
            atomicExch(&g_desc[b], ((unsigned long long)agg << 2) | 1ULL);
            int p = b - 1;
            long long run = 0;
            while (true) {
                unsigned long long d = atomicAdd(&g_desc[p], 0ULL);
                unsigned st = (unsigned)(d & 3ULL);
                if (st == 0u) continue;                 // predecessor not ready
                long long val = (long long)(d >> 2);
                if (st == 2u) { epref = run + val; break; }
                run += val; p--;                        // aggregate: keep walking
            }
            atomicExch(&g_desc[b], ((unsigned long long)(epref + agg) << 2) | 2ULL);
        }
        s_pref = (int)epref;
    }
    __syncthreads();
    if (i < N_NODES) {
        int o = s_pref + s[tid] - v;   // exclusive prefix
        g_off[i] = o;
        g_cur[i] = o;
    }
}

// ---------------- fill CSR (edges + self loops); also zero pool ----------
__global__ void k_fill(const int* __restrict__ src, const int* __restrict__ dst) {
    int i = blockIdx.x * blockDim.x + threadIdx.x;
    if (blockIdx.x == 0 && threadIdx.x < D) g_pool[threadIdx.x] = 0.0f;
    if (i >= N_TOT) return;
    int s, d;
    if (i < N_EDGES) { s = src[i]; d = dst[i]; }
    else             { s = i - N_EDGES; d = s; }
    int pos = atomicAdd(&g_cur[d], 1);
    g_esrc[pos] = s;
}

// ---------------- H = X @ W (100k x 64 @ 64 x 64), 8x4 register tile ------
// Writes H in bf16 (halves the attn gather traffic). Epilogue also computes
// ssrc = h.a_src, sdst = h.a_dst per row from the fp32 accumulators.
__global__ __launch_bounds__(256, 2) void k_gemm(const float* __restrict__ X,
                                                 const float* __restrict__ W,
                                                 const float* __restrict__ asrc,
                                                 const float* __restrict__ adst,
                                                 __nv_bfloat16* __restrict__ H) {
    __shared__ __align__(16) float4 sW[64 * 16];   // [k][colgroup]
    __shared__ __align__(16) float4 sX[TM * 16];   // [row][k4]
    int tid = threadIdx.x;
    const float4* W4 = (const float4*)W;
    for (int i = tid; i < 64 * 16; i += 256) sW[i] = W4[i];

    int base = blockIdx.x * TM;
    const float4* X4 = (const float4*)X;
    for (int i = tid; i < TM * 16; i += 256) {
        int row = base + (i >> 4);
        sX[i] = (row < N_NODES) ? X4[(size_t)base * 16 + i]
                                : make_float4(0.f, 0.f, 0.f, 0.f);
    }
    __syncthreads();

    int cg = tid & 15;    // col group: cols 4*cg..4*cg+3
    int rg = tid >> 4;    // row group: rows 8*rg..8*rg+7
    float acc[8][4];
#pragma unroll
    for (int r = 0; r < 8; r++)
#pragma unroll
        for (int c = 0; c < 4; c++) acc[r][c] = 0.0f;

#pragma unroll
    for (int k4 = 0; k4 < 16; k4++) {
        float4 w0 = sW[(k4 * 4 + 0) * 16 + cg];
        float4 w1 = sW[(k4 * 4 + 1) * 16 + cg];
        float4 w2 = sW[(k4 * 4 + 2) * 16 + cg];
        float4 w3 = sW[(k4 * 4 + 3) * 16 + cg];
#pragma unroll
        for (int r = 0; r < 8; r++) {
            float4 xv = sX[(rg * 8 + r) * 16 + k4];
            acc[r][0] += xv.x * w0.x + xv.y * w1.x + xv.z * w2.x + xv.w * w3.x;
            acc[r][1] += xv.x * w0.y + xv.y * w1.y + xv.z * w2.y + xv.w * w3.y;
            acc[r][2] += xv.x * w0.z + xv.y * w1.z + xv.z * w2.z + xv.w * w3.z;
            acc[r][3] += xv.x * w0.w + xv.y * w1.w + xv.z * w2.w + xv.w * w3.w;
        }
    }

    // write H tile as bf16 (4 cols = 8 bytes per thread-row)
#pragma unroll
    for (int r = 0; r < 8; r++) {
        int row = base + rg * 8 + r;
        if (row < N_NODES) {
            __nv_bfloat162 p0 = __floats2bfloat162_rn(acc[r][0], acc[r][1]);
            __nv_bfloat162 p1 = __floats2bfloat162_rn(acc[r][2], acc[r][3]);
            uint2 u;
            u.x = *reinterpret_cast<unsigned int*>(&p0);
            u.y = *reinterpret_cast<unsigned int*>(&p1);
            ((uint2*)H)[(size_t)row * 16 + cg] = u;
        }
    }

    // fused attention dots (fp32): reduce over the 16 lanes of each half-warp
    float4 av = ((const float4*)asrc)[cg];
    float4 dv = ((const float4*)adst)[cg];
    int lane = tid & 31;
#pragma unroll
    for (int r = 0; r < 8; r++) {
        float p = acc[r][0] * av.x + acc[r][1] * av.y +
                  acc[r][2] * av.z + acc[r][3] * av.w;
        float q = acc[r][0] * dv.x + acc[r][1] * dv.y +
                  acc[r][2] * dv.z + acc[r][3] * dv.w;
#pragma unroll
        for (int o = 8; o > 0; o >>= 1) {
            p += __shfl_xor_sync(0xffffffffu, p, o);
            q += __shfl_xor_sync(0xffffffffu, q, o);
        }
        if ((lane & 15) == 0) {
            int row = base + rg * 8 + r;
            if (row < N_NODES) { g_ssrc[row] = p; g_sdst[row] = q; }
        }
    }
}

// ---------------- fused single-pass softmax + aggregation ----------------
// One warp per dst node; gathers bf16 h rows (128 B/edge). Inner broadcast
// loop unrolled x4 for MLP.
template <bool DO_POOL>
__global__ __launch_bounds__(256) void k_attn(const __nv_bfloat16* __restrict__ H,
                                              const float* __restrict__ b,
                                              float* __restrict__ OUT) {
    __shared__ float sp[64];
    if (DO_POOL) {
        if (threadIdx.x < 64) sp[threadIdx.x] = 0.0f;
        __syncthreads();
    }

    int node = (blockIdx.x * blockDim.x + threadIdx.x) >> 5;  // always < N_NODES
    int lane = threadIdx.x & 31;

    int off = g_off[node];
    int deg = g_deg[node];
    float sd = g_sdst[node];
    const __nv_bfloat162* Hb = (const __nv_bfloat162*)H;

    float ax = 0.0f, ay = 0.0f, se = 0.0f;
    for (int jb = 0; jb < deg; jb += 32) {
        int j = jb + lane;
        int s = 0; float ex = 0.0f;
        if (j < deg) {
            s = g_esrc[off + j];
            float e = g_ssrc[s] + sd;
            e = (e > 0.0f) ? e : NEG_SLOPE * e;
            ex = __expf(e);
        }
        se += ex;
        int cnt = min(32, deg - jb);
        int k = 0;
        for (; k + 4 <= cnt; k += 4) {
            int   s0 = __shfl_sync(0xffffffffu, s, k);
            int   s1 = __shfl_sync(0xffffffffu, s, k + 1);
            int   s2 = __shfl_sync(0xffffffffu, s, k + 2);
            int   s3 = __shfl_sync(0xffffffffu, s, k + 3);
            float e0 = __shfl_sync(0xffffffffu, ex, k);
            float e1 = __shfl_sync(0xffffffffu, ex, k + 1);
            float e2 = __shfl_sync(0xffffffffu, ex, k + 2);
            float e3 = __shfl_sync(0xffffffffu, ex, k + 3);
            float2 h0 = __bfloat1622float2(Hb[(size_t)s0 * 32 + lane]);
            float2 h1 = __bfloat1622float2(Hb[(size_t)s1 * 32 + lane]);
            float2 h2 = __bfloat1622float2(Hb[(size_t)s2 * 32 + lane]);
            float2 h3 = __bfloat1622float2(Hb[(size_t)s3 * 32 + lane]);
            ax += e0 * h0.x; ay += e0 * h0.y;
            ax += e1 * h1.x; ay += e1 * h1.y;
            ax += e2 * h2.x; ay += e2 * h2.y;
            ax += e3 * h3.x; ay += e3 * h3.y;
        }
        for (; k < cnt; k++) {
            int   ss  = __shfl_sync(0xffffffffu, s, k);
            float exk = __shfl_sync(0xffffffffu, ex, k);
            float2 hv = __bfloat1622float2(Hb[(size_t)ss * 32 + lane]);
            ax += exk * hv.x;
            ay += exk * hv.y;
        }
    }
#pragma unroll
    for (int o = 16; o > 0; o >>= 1) se += __shfl_xor_sync(0xffffffffu, se, o);
    float inv = 1.0f / (se + EPSV);

    float2 bb = ((const float2*)b)[lane];
    float r0 = fmaxf(ax * inv + bb.x, 0.0f);
    float r1 = fmaxf(ay * inv + bb.y, 0.0f);

    if (!DO_POOL) {
        float2 rv; rv.x = r0; rv.y = r1;
        ((float2*)OUT)[(size_t)node * 32 + lane] = rv;
    } else {
        atomicAdd(&sp[lane * 2],     r0);
        atomicAdd(&sp[lane * 2 + 1], r1);
        __syncthreads();
        if (threadIdx.x < 64) atomicAdd(&g_pool[threadIdx.x], sp[threadIdx.x]);
    }
}

// ---------------- final: out = (pool/N) . W_out + b_out ----------------
__global__ void k_final(const float* __restrict__ Wout,
                        const float* __restrict__ bout,
                        float* __restrict__ out) {
    __shared__ float s[2];
    int t = threadIdx.x;      // 64 threads
    float v = (g_pool[t] * (1.0f / (float)N_NODES)) * Wout[t];
#pragma unroll
    for (int o = 16; o > 0; o >>= 1) v += __shfl_xor_sync(0xffffffffu, v, o);
    if ((t & 31) == 0) s[t >> 5] = v;
    __syncthreads();
    if (t == 0) out[0] = s[0] + s[1] + bout[0];
}

// ---------------- launcher ----------------
extern "C" void kernel_launch(void* const* d_in, const int* in_sizes, int n_in,
                              void* d_out, int out_size) {
    const float* x      = (const float*)d_in[0];
    const int*   eidx   = (const int*)d_in[1];
    const float* W1     = (const float*)d_in[2];
    const float* a_src1 = (const float*)d_in[3];
    const float* a_dst1 = (const float*)d_in[4];
    const float* b1     = (const float*)d_in[5];
    const float* W2     = (const float*)d_in[6];
    const float* a_src2 = (const float*)d_in[7];
    const float* a_dst2 = (const float*)d_in[8];
    const float* b2     = (const float*)d_in[9];
    const float* W_out  = (const float*)d_in[10];
    const float* b_out  = (const float*)d_in[11];
    float* out = (float*)d_out;

    const int* src = eidx;
    const int* dst = eidx + N_EDGES;

    __nv_bfloat16* hA; cudaGetSymbolAddress((void**)&hA, g_hA);
    float* hB;   cudaGetSymbolAddress((void**)&hB, g_hB);
    int*   degp; cudaGetSymbolAddress((void**)&degp, g_deg);

    // persistent secondary stream + events (host objects, created once).
    static cudaStream_t sB = nullptr;
    static cudaEvent_t evFork = nullptr, evJoin = nullptr;
    if (sB == nullptr) {
        cudaStreamCreateWithFlags(&sB, cudaStreamNonBlocking);
        cudaEventCreateWithFlags(&evFork, cudaEventDisableTiming);
        cudaEventCreateWithFlags(&evJoin, cudaEventDisableTiming);
    }

    int nbGemm = (N_NODES + TM - 1) / TM;   // 782
    int nbWarp = (N_NODES * 32) / 256;      // 12500 (exact)

    // fork point: sB depends only on stream-0 state at capture begin
    cudaEventRecord(evFork, 0);
    cudaStreamWaitEvent(sB, evFork, 0);

    // ---- CSR build on stream 0 (launch indices 0..3) ----
    cudaMemsetAsync(degp, 0, N_NODES * sizeof(int), 0);          // 0
    k_count<<<(N_EDGES + 255) / 256, 256>>>(dst);                // 1
    k_scanall<<<NB_SCAN, 1024>>>();                              // 2
    k_fill<<<(N_TOT + 255) / 256, 256>>>(src, dst);              // 3

    // ---- gemm1 on sB, concurrent with the CSR chain ----
    k_gemm<<<nbGemm, 256, 0, sB>>>(x, W1, a_src1, a_dst1, hA);   // 4
    cudaEventRecord(evJoin, sB);
    cudaStreamWaitEvent(0, evJoin, 0);

    // ---- attn1 = launch index 5 -> profiled by ncu -s 5 -c 1 ----
    k_attn<false><<<nbWarp, 256>>>(hA, b1, hB);                  // 5

    // layer 2: hB -> hA -> (pool)
    k_gemm<<<nbGemm, 256>>>(hB, W2, a_src2, a_dst2, hA);         // 6
    k_attn<true><<<nbWarp, 256>>>(hA, b2, nullptr);              // 7

    k_final<<<1, 64>>>(W_out, b_out, out);                       // 8
}

// round 11
// speedup vs baseline: 1.3825x; 1.0185x over previous
#include <cuda_runtime.h>
#include <cuda_bf16.h>
#include <math_constants.h>

#define N_NODES 100000
#define N_EDGES 1200000
#define N_TOT   1300000   // edges + self loops
#define D 64
#define NEG_SLOPE 0.2f
#define EPSV 1e-16f
#define TM 128            // gemm rows per block
#define NB_SCAN 98        // ceil(N_NODES/1024)

// ---------------- device scratch (static, no allocations) ----------------
__device__ __nv_bfloat16 g_hA[N_NODES * D];   // gathered operand, bf16
__device__ float g_hB[N_NODES * D];           // attn1 output (gemm2 input), fp32
__device__ float g_ssrc[N_NODES];
__device__ float g_sdst[N_NODES];
__device__ int   g_deg[N_NODES];
__device__ int   g_off[N_NODES];
__device__ int   g_cur[N_NODES];
__device__ int   g_esrc[N_TOT];
__device__ unsigned long long g_desc[128];    // decoupled-lookback descriptors
__device__ float g_pool[D];

// ---------------- count incoming edges per dst (incl. self loops) ---------
// Also resets the scan descriptors (runs before k_scanall in stream order).
__global__ void k_count(const int* __restrict__ dst) {
    int i = blockIdx.x * blockDim.x + threadIdx.x;
    if (i < 128) g_desc[i] = 0ULL;
    if (i < N_EDGES) atomicAdd(&g_deg[dst[i]], 1);
    if (i < N_NODES) atomicAdd(&g_deg[i], 1);   // self loop
}

// ---------------- single-kernel exclusive scan (decoupled lookback) -------
// 98 blocks x 1024 threads, all resident in one wave (98 < 148 SMs), so the
// spin on predecessor descriptors cannot deadlock. Descriptor packs
// (value<<2)|state, state: 0=invalid, 1=aggregate, 2=inclusive-prefix.
__global__ void k_scanall() {
    __shared__ int s[1024];
    __shared__ int s_pref;
    int tid = threadIdx.x, b = blockIdx.x;
    int i = b * 1024 + tid;
    int v = (i < N_NODES) ? g_deg[i] : 0;
    s[tid] = v;
    __syncthreads();
    for (int off = 1; off < 1024; off <<= 1) {
        int t = (tid >= off) ? s[tid - off] : 0;
        __syncthreads();
        s[tid] += t;
        __syncthreads();
    }
    int agg = s[1023];
    if (tid == 0) {
        long long epref = 0;
        if (b == 0) {
            atomicExch(&g_desc[0], ((unsigned long long)agg << 2) | 2ULL);
        } else {
            atomicExch(&g_desc[b], ((unsigned long long)agg << 2) | 1ULL);
            int p = b - 1;
            long long run = 0;
            while (true) {
                unsigned long long d = atomicAdd(&g_desc[p], 0ULL);
                unsigned st = (unsigned)(d & 3ULL);
                if (st == 0u) continue;                 // predecessor not ready
                long long val = (long long)(d >> 2);
                if (st == 2u) { epref = run + val; break; }
                run += val; p--;                        // aggregate: keep walking
            }
            atomicExch(&g_desc[b], ((unsigned long long)(epref + agg) << 2) | 2ULL);
        }
        s_pref = (int)epref;
    }
    __syncthreads();
    if (i < N_NODES) {
        int o = s_pref + s[tid] - v;   // exclusive prefix
        g_off[i] = o;
        g_cur[i] = o;
    }
}

// ---------------- fill CSR (edges + self loops) ----------------
__global__ void k_fill(const int* __restrict__ src, const int* __restrict__ dst) {
    int i = blockIdx.x * blockDim.x + threadIdx.x;
    if (i >= N_TOT) return;
    int s, d;
    if (i < N_EDGES) { s = src[i]; d = dst[i]; }
    else             { s = i - N_EDGES; d = s; }
    int pos = atomicAdd(&g_cur[d], 1);
    g_esrc[pos] = s;
}

// ---------------- zero the pool accumulator (also a profiler spacer) ------
__global__ void k_zeropool() {
    if (threadIdx.x < D) g_pool[threadIdx.x] = 0.0f;
}

// ---------------- H = X @ W (100k x 64 @ 64 x 64), 8x4 register tile ------
// Writes H in bf16 (halves the attn gather traffic). Epilogue also computes
// ssrc = h.a_src, sdst = h.a_dst per row from the fp32 accumulators.
// launch_bounds(256,3): cap regs at 85 so 3 CTAs (24 warps) fit per SM and
// the LDS->FFMA latency chains are covered (round-8 profile: occ=22.7%,
// issue=50% at 2 CTAs).
__global__ __launch_bounds__(256, 3) void k_gemm(const float* __restrict__ X,
                                                 const float* __restrict__ W,
                                                 const float* __restrict__ asrc,
                                                 const float* __restrict__ adst,
                                                 __nv_bfloat16* __restrict__ H) {
    __shared__ __align__(16) float4 sW[64 * 16];   // [k][colgroup]
    __shared__ __align__(16) float4 sX[TM * 16];   // [row][k4]
    int tid = threadIdx.x;
    const float4* W4 = (const float4*)W;
    for (int i = tid; i < 64 * 16; i += 256) sW[i] = W4[i];

    int base = blockIdx.x * TM;
    const float4* X4 = (const float4*)X;
    for (int i = tid; i < TM * 16; i += 256) {
        int row = base + (i >> 4);
        sX[i] = (row < N_NODES) ? X4[(size_t)base * 16 + i]
                                : make_float4(0.f, 0.f, 0.f, 0.f);
    }
    __syncthreads();

    int cg = tid & 15;    // col group: cols 4*cg..4*cg+3
    int rg = tid >> 4;    // row group: rows 8*rg..8*rg+7
    float acc[8][4];
#pragma unroll
    for (int r = 0; r < 8; r++)
#pragma unroll
        for (int c = 0; c < 4; c++) acc[r][c] = 0.0f;

#pragma unroll
    for (int k4 = 0; k4 < 16; k4++) {
        float4 w0 = sW[(k4 * 4 + 0) * 16 + cg];
        float4 w1 = sW[(k4 * 4 + 1) * 16 + cg];
        float4 w2 = sW[(k4 * 4 + 2) * 16 + cg];
        float4 w3 = sW[(k4 * 4 + 3) * 16 + cg];
#pragma unroll
        for (int r = 0; r < 8; r++) {
            float4 xv = sX[(rg * 8 + r) * 16 + k4];
            acc[r][0] += xv.x * w0.x + xv.y * w1.x + xv.z * w2.x + xv.w * w3.x;
            acc[r][1] += xv.x * w0.y + xv.y * w1.y + xv.z * w2.y + xv.w * w3.y;
            acc[r][2] += xv.x * w0.z + xv.y * w1.z + xv.z * w2.z + xv.w * w3.z;
            acc[r][3] += xv.x * w0.w + xv.y * w1.w + xv.z * w2.w + xv.w * w3.w;
        }
    }

    // write H tile as bf16 (4 cols = 8 bytes per thread-row)
#pragma unroll
    for (int r = 0; r < 8; r++) {
        int row = base + rg * 8 + r;
        if (row < N_NODES) {
            __nv_bfloat162 p0 = __floats2bfloat162_rn(acc[r][0], acc[r][1]);
            __nv_bfloat162 p1 = __floats2bfloat162_rn(acc[r][2], acc[r][3]);
            uint2 u;
            u.x = *reinterpret_cast<unsigned int*>(&p0);
            u.y = *reinterpret_cast<unsigned int*>(&p1);
            ((uint2*)H)[(size_t)row * 16 + cg] = u;
        }
    }

    // fused attention dots (fp32): reduce over the 16 lanes of each half-warp
    float4 av = ((const float4*)asrc)[cg];
    float4 dv = ((const float4*)adst)[cg];
    int lane = tid & 31;
#pragma unroll
    for (int r = 0; r < 8; r++) {
        float p = acc[r][0] * av.x + acc[r][1] * av.y +
                  acc[r][2] * av.z + acc[r][3] * av.w;
        float q = acc[r][0] * dv.x + acc[r][1] * dv.y +
                  acc[r][2] * dv.z + acc[r][3] * dv.w;
#pragma unroll
        for (int o = 8; o > 0; o >>= 1) {
            p += __shfl_xor_sync(0xffffffffu, p, o);
            q += __shfl_xor_sync(0xffffffffu, q, o);
        }
        if ((lane & 15) == 0) {
            int row = base + rg * 8 + r;
            if (row < N_NODES) { g_ssrc[row] = p; g_sdst[row] = q; }
        }
    }
}

// ---------------- fused single-pass softmax + aggregation ----------------
// One warp per dst node; gathers bf16 h rows (128 B/edge). Inner broadcast
// loop unrolled x4 for MLP.
template <bool DO_POOL>
__global__ __launch_bounds__(256) void k_attn(const __nv_bfloat16* __restrict__ H,
                                              const float* __restrict__ b,
                                              float* __restrict__ OUT) {
    __shared__ float sp[64];
    if (DO_POOL) {
        if (threadIdx.x < 64) sp[threadIdx.x] = 0.0f;
        __syncthreads();
    }

    int node = (blockIdx.x * blockDim.x + threadIdx.x) >> 5;  // always < N_NODES
    int lane = threadIdx.x & 31;

    int off = g_off[node];
    int deg = g_deg[node];
    float sd = g_sdst[node];
    const __nv_bfloat162* Hb = (const __nv_bfloat162*)H;

    float ax = 0.0f, ay = 0.0f, se = 0.0f;
    for (int jb = 0; jb < deg; jb += 32) {
        int j = jb + lane;
        int s = 0; float ex = 0.0f;
        if (j < deg) {
            s = g_esrc[off + j];
            float e = g_ssrc[s] + sd;
            e = (e > 0.0f) ? e : NEG_SLOPE * e;
            ex = __expf(e);
        }
        se += ex;
        int cnt = min(32, deg - jb);
        int k = 0;
        for (; k + 4 <= cnt; k += 4) {
            int   s0 = __shfl_sync(0xffffffffu, s, k);
            int   s1 = __shfl_sync(0xffffffffu, s, k + 1);
            int   s2 = __shfl_sync(0xffffffffu, s, k + 2);
            int   s3 = __shfl_sync(0xffffffffu, s, k + 3);
            float e0 = __shfl_sync(0xffffffffu, ex, k);
            float e1 = __shfl_sync(0xffffffffu, ex, k + 1);
            float e2 = __shfl_sync(0xffffffffu, ex, k + 2);
            float e3 = __shfl_sync(0xffffffffu, ex, k + 3);
            float2 h0 = __bfloat1622float2(Hb[(size_t)s0 * 32 + lane]);
            float2 h1 = __bfloat1622float2(Hb[(size_t)s1 * 32 + lane]);
            float2 h2 = __bfloat1622float2(Hb[(size_t)s2 * 32 + lane]);
            float2 h3 = __bfloat1622float2(Hb[(size_t)s3 * 32 + lane]);
            ax += e0 * h0.x; ay += e0 * h0.y;
            ax += e1 * h1.x; ay += e1 * h1.y;
            ax += e2 * h2.x; ay += e2 * h2.y;
            ax += e3 * h3.x; ay += e3 * h3.y;
        }
        for (; k < cnt; k++) {
            int   ss  = __shfl_sync(0xffffffffu, s, k);
            float exk = __shfl_sync(0xffffffffu, ex, k);
            float2 hv = __bfloat1622float2(Hb[(size_t)ss * 32 + lane]);
            ax += exk * hv.x;
            ay += exk * hv.y;
        }
    }
#pragma unroll
    for (int o = 16; o > 0; o >>= 1) se += __shfl_xor_sync(0xffffffffu, se, o);
    float inv = 1.0f / (se + EPSV);

    float2 bb = ((const float2*)b)[lane];
    float r0 = fmaxf(ax * inv + bb.x, 0.0f);
    float r1 = fmaxf(ay * inv + bb.y, 0.0f);

    if (!DO_POOL) {
        float2 rv; rv.x = r0; rv.y = r1;
        ((float2*)OUT)[(size_t)node * 32 + lane] = rv;
    } else {
        atomicAdd(&sp[lane * 2],     r0);
        atomicAdd(&sp[lane * 2 + 1], r1);
        __syncthreads();
        if (threadIdx.x < 64) atomicAdd(&g_pool[threadIdx.x], sp[threadIdx.x]);
    }
}

// ---------------- final: out = (pool/N) . W_out + b_out ----------------
__global__ void k_final(const float* __restrict__ Wout,
                        const float* __restrict__ bout,
                        float* __restrict__ out) {
    __shared__ float s[2];
    int t = threadIdx.x;      // 64 threads
    float v = (g_pool[t] * (1.0f / (float)N_NODES)) * Wout[t];
#pragma unroll
    for (int o = 16; o > 0; o >>= 1) v += __shfl_xor_sync(0xffffffffu, v, o);
    if ((t & 31) == 0) s[t >> 5] = v;
    __syncthreads();
    if (t == 0) out[0] = s[0] + s[1] + bout[0];
}

// ---------------- launcher ----------------
extern "C" void kernel_launch(void* const* d_in, const int* in_sizes, int n_in,
                              void* d_out, int out_size) {
    const float* x      = (const float*)d_in[0];
    const int*   eidx   = (const int*)d_in[1];
    const float* W1     = (const float*)d_in[2];
    const float* a_src1 = (const float*)d_in[3];
    const float* a_dst1 = (const float*)d_in[4];
    const float* b1     = (const float*)d_in[5];
    const float* W2     = (const float*)d_in[6];
    const float* a_src2 = (const float*)d_in[7];
    const float* a_dst2 = (const float*)d_in[8];
    const float* b2     = (const float*)d_in[9];
    const float* W_out  = (const float*)d_in[10];
    const float* b_out  = (const float*)d_in[11];
    float* out = (float*)d_out;

    const int* src = eidx;
    const int* dst = eidx + N_EDGES;

    __nv_bfloat16* hA; cudaGetSymbolAddress((void**)&hA, g_hA);
    float* hB;   cudaGetSymbolAddress((void**)&hB, g_hB);
    int*   degp; cudaGetSymbolAddress((void**)&degp, g_deg);

    // persistent secondary stream + events (host objects, created once).
    static cudaStream_t sB = nullptr;
    static cudaEvent_t evFork = nullptr, evJoin = nullptr;
    if (sB == nullptr) {
        cudaStreamCreateWithFlags(&sB, cudaStreamNonBlocking);
        cudaEventCreateWithFlags(&evFork, cudaEventDisableTiming);
        cudaEventCreateWithFlags(&evJoin, cudaEventDisableTiming);
    }

    int nbGemm = (N_NODES + TM - 1) / TM;   // 782
    int nbWarp = (N_NODES * 32) / 256;      // 12500 (exact)

    // fork point: sB depends only on stream-0 state at capture begin
    cudaEventRecord(evFork, 0);
    cudaStreamWaitEvent(sB, evFork, 0);

    // ---- CSR build on stream 0 (kernel launch indices 0..2) ----
    cudaMemsetAsync(degp, 0, N_NODES * sizeof(int), 0);          // (memset: not counted)
    k_count<<<(N_EDGES + 255) / 256, 256>>>(dst);                // 0
    k_scanall<<<NB_SCAN, 1024>>>();                              // 1
    k_fill<<<(N_TOT + 255) / 256, 256>>>(src, dst);              // 2

    // ---- gemm1 on sB, concurrent with the CSR chain ----
    k_gemm<<<nbGemm, 256, 0, sB>>>(x, W1, a_src1, a_dst1, hA);   // 3
    // spacer/pool-zero on stream 0 so attn1 lands at kernel index 5
    k_zeropool<<<1, 64>>>();                                     // 4
    cudaEventRecord(evJoin, sB);
    cudaStreamWaitEvent(0, evJoin, 0);

    // ---- attn1 = kernel index 5 -> profiled by ncu -s 5 -c 1 ----
    k_attn<false><<<nbWarp, 256>>>(hA, b1, hB);                  // 5

    // layer 2: hB -> hA -> (pool)
    k_gemm<<<nbGemm, 256>>>(hB, W2, a_src2, a_dst2, hA);         // 6
    k_attn<true><<<nbWarp, 256>>>(hA, b2, nullptr);              // 7

    k_final<<<1, 64>>>(W_out, b_out, out);                       // 8
}

// round 12
// speedup vs baseline: 1.7375x; 1.2568x over previous
#include <cuda_runtime.h>
#include <cuda_bf16.h>
#include <math_constants.h>

#define N_NODES 100000
#define N_EDGES 1200000
#define N_TOT   1300000   // edges + self loops
#define D 64
#define NEG_SLOPE 0.2f
#define EPSV 1e-16f
#define TM 128            // gemm rows per block
#define NB_SCAN 98        // ceil(N_NODES/1024)
#define FULLM 0xffffffffu

// ---------------- device scratch (static, no allocations) ----------------
__device__ __nv_bfloat16 g_hA[N_NODES * D];   // gathered operand, bf16
__device__ float g_hB[N_NODES * D];           // attn1 output (gemm2 input), fp32
__device__ float g_ssrc[N_NODES];
__device__ float g_sdst[N_NODES];
__device__ int   g_deg[N_NODES];
__device__ int   g_off[N_NODES];
__device__ int   g_cur[N_NODES];
__device__ int   g_esrc[N_TOT];
__device__ unsigned long long g_desc[128];    // decoupled-lookback descriptors
__device__ float g_pool[D];

// exact bf16 -> f32 unpack (bf16 is the top half of f32)
__device__ __forceinline__ float bflo(unsigned u) { return __uint_as_float(u << 16); }
__device__ __forceinline__ float bfhi(unsigned u) { return __uint_as_float(u & 0xffff0000u); }

// ---------------- count incoming edges per dst (incl. self loops) ---------
// Also resets the scan descriptors and the pool accumulator.
__global__ void k_count(const int* __restrict__ dst) {
    int i = blockIdx.x * blockDim.x + threadIdx.x;
    if (i < 128) g_desc[i] = 0ULL;
    if (i < D) g_pool[i] = 0.0f;
    if (i < N_EDGES) atomicAdd(&g_deg[dst[i]], 1);
    if (i < N_NODES) atomicAdd(&g_deg[i], 1);   // self loop
}

// ---------------- single-kernel exclusive scan (decoupled lookback) -------
// 98 blocks x 1024 threads, one wave (98 < 148 SMs) -> spin cannot deadlock.
__global__ void k_scanall() {
    __shared__ int s[1024];
    __shared__ int s_pref;
    int tid = threadIdx.x, b = blockIdx.x;
    int i = b * 1024 + tid;
    int v = (i < N_NODES) ? g_deg[i] : 0;
    s[tid] = v;
    __syncthreads();
    for (int off = 1; off < 1024; off <<= 1) {
        int t = (tid >= off) ? s[tid - off] : 0;
        __syncthreads();
        s[tid] += t;
        __syncthreads();
    }
    int agg = s[1023];
    if (tid == 0) {
        long long epref = 0;
        if (b == 0) {
            atomicExch(&g_desc[0], ((unsigned long long)agg << 2) | 2ULL);
        } else {
            atomicExch(&g_desc[b], ((unsigned long long)agg << 2) | 1ULL);
            int p = b - 1;
            long long run = 0;
            while (true) {
                unsigned long long d = atomicAdd(&g_desc[p], 0ULL);
                unsigned st = (unsigned)(d & 3ULL);
                if (st == 0u) continue;
                long long val = (long long)(d >> 2);
                if (st == 2u) { epref = run + val; break; }
                run += val; p--;
            }
            atomicExch(&g_desc[b], ((unsigned long long)(epref + agg) << 2) | 2ULL);
        }
        s_pref = (int)epref;
    }
    __syncthreads();
    if (i < N_NODES) {
        int o = s_pref + s[tid] - v;
        g_off[i] = o;
        g_cur[i] = o;
    }
}

// ---------------- fill CSR (edges + self loops) ----------------
__global__ void k_fill(const int* __restrict__ src, const int* __restrict__ dst) {
    int i = blockIdx.x * blockDim.x + threadIdx.x;
    if (i >= N_TOT) return;
    int s, d;
    if (i < N_EDGES) { s = src[i]; d = dst[i]; }
    else             { s = i - N_EDGES; d = s; }
    int pos = atomicAdd(&g_cur[d], 1);
    g_esrc[pos] = s;
}

// ---------------- H = X @ W (100k x 64 @ 64 x 64), 8x4 register tile ------
__global__ __launch_bounds__(256, 3) void k_gemm(const float* __restrict__ X,
                                                 const float* __restrict__ W,
                                                 const float* __restrict__ asrc,
                                                 const float* __restrict__ adst,
                                                 __nv_bfloat16* __restrict__ H) {
    __shared__ __align__(16) float4 sW[64 * 16];   // [k][colgroup]
    __shared__ __align__(16) float4 sX[TM * 16];   // [row][k4]
    int tid = threadIdx.x;
    const float4* W4 = (const float4*)W;
    for (int i = tid; i < 64 * 16; i += 256) sW[i] = W4[i];

    int base = blockIdx.x * TM;
    const float4* X4 = (const float4*)X;
    for (int i = tid; i < TM * 16; i += 256) {
        int row = base + (i >> 4);
        sX[i] = (row < N_NODES) ? X4[(size_t)base * 16 + i]
                                : make_float4(0.f, 0.f, 0.f, 0.f);
    }
    __syncthreads();

    int cg = tid & 15;
    int rg = tid >> 4;
    float acc[8][4];
#pragma unroll
    for (int r = 0; r < 8; r++)
#pragma unroll
        for (int c = 0; c < 4; c++) acc[r][c] = 0.0f;

#pragma unroll
    for (int k4 = 0; k4 < 16; k4++) {
        float4 w0 = sW[(k4 * 4 + 0) * 16 + cg];
        float4 w1 = sW[(k4 * 4 + 1) * 16 + cg];
        float4 w2 = sW[(k4 * 4 + 2) * 16 + cg];
        float4 w3 = sW[(k4 * 4 + 3) * 16 + cg];
#pragma unroll
        for (int r = 0; r < 8; r++) {
            float4 xv = sX[(rg * 8 + r) * 16 + k4];
            acc[r][0] += xv.x * w0.x + xv.y * w1.x + xv.z * w2.x + xv.w * w3.x;
            acc[r][1] += xv.x * w0.y + xv.y * w1.y + xv.z * w2.y + xv.w * w3.y;
            acc[r][2] += xv.x * w0.z + xv.y * w1.z + xv.z * w2.z + xv.w * w3.z;
            acc[r][3] += xv.x * w0.w + xv.y * w1.w + xv.z * w2.w + xv.w * w3.w;
        }
    }

#pragma unroll
    for (int r = 0; r < 8; r++) {
        int row = base + rg * 8 + r;
        if (row < N_NODES) {
            __nv_bfloat162 p0 = __floats2bfloat162_rn(acc[r][0], acc[r][1]);
            __nv_bfloat162 p1 = __floats2bfloat162_rn(acc[r][2], acc[r][3]);
            uint2 u;
            u.x = *reinterpret_cast<unsigned int*>(&p0);
            u.y = *reinterpret_cast<unsigned int*>(&p1);
            ((uint2*)H)[(size_t)row * 16 + cg] = u;
        }
    }

    float4 av = ((const float4*)asrc)[cg];
    float4 dv = ((const float4*)adst)[cg];
    int lane = tid & 31;
#pragma unroll
    for (int r = 0; r < 8; r++) {
        float p = acc[r][0] * av.x + acc[r][1] * av.y +
                  acc[r][2] * av.z + acc[r][3] * av.w;
        float q = acc[r][0] * dv.x + acc[r][1] * dv.y +
                  acc[r][2] * dv.z + acc[r][3] * dv.w;
#pragma unroll
        for (int o = 8; o > 0; o >>= 1) {
            p += __shfl_xor_sync(FULLM, p, o);
            q += __shfl_xor_sync(FULLM, q, o);
        }
        if ((lane & 15) == 0) {
            int row = base + rg * 8 + r;
            if (row < N_NODES) { g_ssrc[row] = p; g_sdst[row] = q; }
        }
    }
}

// ---------------- fused softmax + aggregation: 4 nodes per warp -----------
// 8 lanes per node; each lane owns 8 dims (one uint4 = 8 bf16 per gather).
// One LDG.128 fetches 4 edges' rows; one width-8 shfl broadcasts per value
// for all 4 subgroups. Loop bound = warp-max degree; padded slots have ex=0
// and skip the gather (subgroup-uniform predicate).
template <bool DO_POOL>
__global__ __launch_bounds__(256) void k_attn(const __nv_bfloat16* __restrict__ H,
                                              const float* __restrict__ b,
                                              float* __restrict__ OUT) {
    __shared__ float sp[64];
    if (DO_POOL) {
        if (threadIdx.x < 64) sp[threadIdx.x] = 0.0f;
        __syncthreads();
    }

    int tid = threadIdx.x;
    int lane = tid & 31;
    int slane = lane & 7;            // lane within subgroup (owns dims 8*slane..)
    int node = (blockIdx.x * 256 + tid) >> 3;   // 800000/8 threads -> always valid

    int off = g_off[node];
    int deg = g_deg[node];
    float sd = g_sdst[node];

    // warp-wide max degree (deg uniform within a subgroup)
    int degmax = deg;
    degmax = max(degmax, __shfl_xor_sync(FULLM, degmax, 8));
    degmax = max(degmax, __shfl_xor_sync(FULLM, degmax, 16));

    const uint4* H4 = (const uint4*)H;   // 8 uint4 per 64-dim bf16 row

    float acc[8];
#pragma unroll
    for (int i = 0; i < 8; i++) acc[i] = 0.0f;
    float se = 0.0f;

    for (int jb = 0; jb < degmax; jb += 8) {
        int j = jb + slane;
        int s = 0; float ex = 0.0f;
        if (j < deg) {
            s = g_esrc[off + j];
            float e = g_ssrc[s] + sd;
            e = (e > 0.0f) ? e : NEG_SLOPE * e;
            ex = __expf(e);
        }
        se += ex;
#pragma unroll
        for (int k = 0; k < 8; k++) {
            float exk = __shfl_sync(FULLM, ex, k, 8);
            int   ss  = __shfl_sync(FULLM, s,  k, 8);
            if (exk > 0.0f) {
                uint4 v = H4[(size_t)ss * 8 + slane];
                acc[0] += exk * bflo(v.x);
                acc[1] += exk * bfhi(v.x);
                acc[2] += exk * bflo(v.y);
                acc[3] += exk * bfhi(v.y);
                acc[4] += exk * bflo(v.z);
                acc[5] += exk * bfhi(v.z);
                acc[6] += exk * bflo(v.w);
                acc[7] += exk * bfhi(v.w);
            }
        }
    }

    // denominator: reduce within subgroup (offsets 1,2,4 stay inside)
    se += __shfl_xor_sync(FULLM, se, 1);
    se += __shfl_xor_sync(FULLM, se, 2);
    se += __shfl_xor_sync(FULLM, se, 4);
    float inv = 1.0f / (se + EPSV);

    float4 b0 = ((const float4*)b)[slane * 2];
    float4 b1 = ((const float4*)b)[slane * 2 + 1];
    float r[8];
    r[0] = fmaxf(acc[0] * inv + b0.x, 0.0f);
    r[1] = fmaxf(acc[1] * inv + b0.y, 0.0f);
    r[2] = fmaxf(acc[2] * inv + b0.z, 0.0f);
    r[3] = fmaxf(acc[3] * inv + b0.w, 0.0f);
    r[4] = fmaxf(acc[4] * inv + b1.x, 0.0f);
    r[5] = fmaxf(acc[5] * inv + b1.y, 0.0f);
    r[6] = fmaxf(acc[6] * inv + b1.z, 0.0f);
    r[7] = fmaxf(acc[7] * inv + b1.w, 0.0f);

    if (!DO_POOL) {
        float4 o0 = make_float4(r[0], r[1], r[2], r[3]);
        float4 o1 = make_float4(r[4], r[5], r[6], r[7]);
        ((float4*)OUT)[(size_t)node * 16 + slane * 2]     = o0;
        ((float4*)OUT)[(size_t)node * 16 + slane * 2 + 1] = o1;
    } else {
        // sum the 4 nodes of this warp (same slane = same dims across subgroups)
#pragma unroll
        for (int i = 0; i < 8; i++) {
            r[i] += __shfl_xor_sync(FULLM, r[i], 8);
            r[i] += __shfl_xor_sync(FULLM, r[i], 16);
        }
        if (lane < 8) {
#pragma unroll
            for (int i = 0; i < 8; i++)
                atomicAdd(&sp[slane * 8 + i], r[i]);
        }
        __syncthreads();
        if (tid < 64) atomicAdd(&g_pool[tid], sp[tid]);
    }
}

// ---------------- final: out = (pool/N) . W_out + b_out ----------------
__global__ void k_final(const float* __restrict__ Wout,
                        const float* __restrict__ bout,
                        float* __restrict__ out) {
    __shared__ float s[2];
    int t = threadIdx.x;      // 64 threads
    float v = (g_pool[t] * (1.0f / (float)N_NODES)) * Wout[t];
#pragma unroll
    for (int o = 16; o > 0; o >>= 1) v += __shfl_xor_sync(FULLM, v, o);
    if ((t & 31) == 0) s[t >> 5] = v;
    __syncthreads();
    if (t == 0) out[0] = s[0] + s[1] + bout[0];
}

// ---------------- launcher ----------------
extern "C" void kernel_launch(void* const* d_in, const int* in_sizes, int n_in,
                              void* d_out, int out_size) {
    const float* x      = (const float*)d_in[0];
    const int*   eidx   = (const int*)d_in[1];
    const float* W1     = (const float*)d_in[2];
    const float* a_src1 = (const float*)d_in[3];
    const float* a_dst1 = (const float*)d_in[4];
    const float* b1     = (const float*)d_in[5];
    const float* W2     = (const float*)d_in[6];
    const float* a_src2 = (const float*)d_in[7];
    const float* a_dst2 = (const float*)d_in[8];
    const float* b2     = (const float*)d_in[9];
    const float* W_out  = (const float*)d_in[10];
    const float* b_out  = (const float*)d_in[11];
    float* out = (float*)d_out;

    const int* src = eidx;
    const int* dst = eidx + N_EDGES;

    __nv_bfloat16* hA; cudaGetSymbolAddress((void**)&hA, g_hA);
    float* hB;   cudaGetSymbolAddress((void**)&hB, g_hB);
    int*   degp; cudaGetSymbolAddress((void**)&degp, g_deg);

    static cudaStream_t sB = nullptr;
    static cudaEvent_t evFork = nullptr, evJoin = nullptr;
    if (sB == nullptr) {
        cudaStreamCreateWithFlags(&sB, cudaStreamNonBlocking);
        cudaEventCreateWithFlags(&evFork, cudaEventDisableTiming);
        cudaEventCreateWithFlags(&evJoin, cudaEventDisableTiming);
    }

    int nbGemm = (N_NODES + TM - 1) / TM;   // 782
    int nbAttn = (N_NODES * 8) / 256;       // 3125 (exact)

    cudaEventRecord(evFork, 0);
    cudaStreamWaitEvent(sB, evFork, 0);

    // ---- CSR build on stream 0 ----
    cudaMemsetAsync(degp, 0, N_NODES * sizeof(int), 0);
    k_count<<<(N_EDGES + 255) / 256, 256>>>(dst);
    k_scanall<<<NB_SCAN, 1024>>>();
    k_fill<<<(N_TOT + 255) / 256, 256>>>(src, dst);

    // ---- gemm1 on sB, concurrent with the CSR chain ----
    k_gemm<<<nbGemm, 256, 0, sB>>>(x, W1, a_src1, a_dst1, hA);
    cudaEventRecord(evJoin, sB);
    cudaStreamWaitEvent(0, evJoin, 0);

    // layer 1 aggregate
    k_attn<false><<<nbAttn, 256>>>(hA, b1, hB);

    // layer 2
    k_gemm<<<nbGemm, 256>>>(hB, W2, a_src2, a_dst2, hA);
    k_attn<true><<<nbAttn, 256>>>(hA, b2, nullptr);

    k_final<<<1, 64>>>(W_out, b_out, out);
}

// round 13
// speedup vs baseline: 1.8200x; 1.0475x over previous
#include <cuda_runtime.h>
#include <cuda_bf16.h>
#include <math_constants.h>

#define N_NODES 100000
#define N_EDGES 1200000
#define N_TOT   1300000   // edges + self loops
#define D 64
#define NEG_SLOPE 0.2f
#define EPSV 1e-16f
#define TM 128            // gemm rows per block
#define XS 68             // sX row stride in floats (padding: conflict-free frags)
#define NB_SCAN 98        // ceil(N_NODES/1024)
#define FULLM 0xffffffffu

// ---------------- device scratch (static, no allocations) ----------------
__device__ __nv_bfloat16 g_hA[N_NODES * D];   // gathered operand, bf16
__device__ float g_hB[N_NODES * D];           // attn1 output (gemm2 input), fp32
__device__ float g_ssrc[N_NODES];
__device__ float g_sdst[N_NODES];
__device__ int   g_deg[N_NODES];
__device__ int   g_off[N_NODES];
__device__ int   g_cur[N_NODES];
__device__ int   g_esrc[N_TOT];
__device__ unsigned long long g_desc[128];    // decoupled-lookback descriptors
__device__ float g_pool[D];

// exact bf16 -> f32 unpack (bf16 is the top half of f32)
__device__ __forceinline__ float bflo(unsigned u) { return __uint_as_float(u << 16); }
__device__ __forceinline__ float bfhi(unsigned u) { return __uint_as_float(u & 0xffff0000u); }

// f32 -> tf32 (round to nearest) kept in a b32 register
__device__ __forceinline__ unsigned f2tf(float f) {
    unsigned u;
    asm("cvt.rna.tf32.f32 %0, %1;" : "=r"(u) : "f"(f));
    return u;
}

// m16n8k8 tf32 MMA, D += A*B
__device__ __forceinline__ void mma_tf32(float* d,
                                         unsigned a0, unsigned a1, unsigned a2, unsigned a3,
                                         unsigned b0, unsigned b1) {
    asm volatile(
        "mma.sync.aligned.m16n8k8.row.col.f32.tf32.tf32.f32 "
        "{%0,%1,%2,%3}, {%4,%5,%6,%7}, {%8,%9}, {%0,%1,%2,%3};"
        : "+f"(d[0]), "+f"(d[1]), "+f"(d[2]), "+f"(d[3])
        : "r"(a0), "r"(a1), "r"(a2), "r"(a3), "r"(b0), "r"(b1));
}

// ---------------- count incoming edges per dst (incl. self loops) ---------
__global__ void k_count(const int* __restrict__ dst) {
    int i = blockIdx.x * blockDim.x + threadIdx.x;
    if (i < 128) g_desc[i] = 0ULL;
    if (i < D) g_pool[i] = 0.0f;
    if (i < N_EDGES) atomicAdd(&g_deg[dst[i]], 1);
    if (i < N_NODES) atomicAdd(&g_deg[i], 1);   // self loop
}

// ---------------- single-kernel exclusive scan (decoupled lookback) -------
__global__ void k_scanall() {
    __shared__ int s[1024];
    __shared__ int s_pref;
    int tid = threadIdx.x, b = blockIdx.x;
    int i = b * 1024 + tid;
    int v = (i < N_NODES) ? g_deg[i] : 0;
    s[tid] = v;
    __syncthreads();
    for (int off = 1; off < 1024; off <<= 1) {
        int t = (tid >= off) ? s[tid - off] : 0;
        __syncthreads();
        s[tid] += t;
        __syncthreads();
    }
    int agg = s[1023];
    if (tid == 0) {
        long long epref = 0;
        if (b == 0) {
            atomicExch(&g_desc[0], ((unsigned long long)agg << 2) | 2ULL);
        } else {
            atomicExch(&g_desc[b], ((unsigned long long)agg << 2) | 1ULL);
            int p = b - 1;
            long long run = 0;
            while (true) {
                unsigned long long d = atomicAdd(&g_desc[p], 0ULL);
                unsigned st = (unsigned)(d & 3ULL);
                if (st == 0u) continue;
                long long val = (long long)(d >> 2);
                if (st == 2u) { epref = run + val; break; }
                run += val; p--;
            }
            atomicExch(&g_desc[b], ((unsigned long long)(epref + agg) << 2) | 2ULL);
        }
        s_pref = (int)epref;
    }
    __syncthreads();
    if (i < N_NODES) {
        int o = s_pref + s[tid] - v;
        g_off[i] = o;
        g_cur[i] = o;
    }
}

// ---------------- fill CSR (edges + self loops) ----------------
__global__ void k_fill(const int* __restrict__ src, const int* __restrict__ dst) {
    int i = blockIdx.x * blockDim.x + threadIdx.x;
    if (i >= N_TOT) return;
    int s, d;
    if (i < N_EDGES) { s = src[i]; d = dst[i]; }
    else             { s = i - N_EDGES; d = s; }
    int pos = atomicAdd(&g_cur[d], 1);
    g_esrc[pos] = s;
}

// ---------------- H = X @ W via tf32 mma.sync (m16n8k8) -------------------
// Block: 128 rows x 64 cols, K=64, 8 warps; warp w owns rows 16w..16w+15.
// A frags from smem (tf32-converted X, stride-68 pad: conflict-free).
// B frags (W, 16KB, L1-hot) direct from global + cvt. fp32 accumulators.
// Epilogue: bf16 H write + fused ssrc/sdst dots in MMA fragment layout.
__global__ __launch_bounds__(256, 3) void k_gemm(const float* __restrict__ X,
                                                 const float* __restrict__ W,
                                                 const float* __restrict__ asrc,
                                                 const float* __restrict__ adst,
                                                 __nv_bfloat16* __restrict__ H) {
    __shared__ __align__(16) unsigned sX[TM * XS];   // 34816 B
    int tid = threadIdx.x;
    int base = blockIdx.x * TM;

    // fill X (tf32-converted), coalesced float4 loads
    const float4* X4 = (const float4*)X;
    for (int i = tid; i < TM * 16; i += 256) {
        int r = i >> 4, c4 = (i & 15) << 2;
        int row = base + r;
        float4 v = (row < N_NODES) ? X4[(size_t)base * 16 + i]
                                   : make_float4(0.f, 0.f, 0.f, 0.f);
        unsigned* p = &sX[r * XS + c4];
        p[0] = f2tf(v.x); p[1] = f2tf(v.y); p[2] = f2tf(v.z); p[3] = f2tf(v.w);
    }
    __syncthreads();

    int warp = tid >> 5, lane = tid & 31;
    int gid = lane >> 2, tig = lane & 3;
    int m0 = warp * 16;

    float d[8][4];
#pragma unroll
    for (int nt = 0; nt < 8; nt++)
#pragma unroll
        for (int c = 0; c < 4; c++) d[nt][c] = 0.0f;

#pragma unroll
    for (int ks = 0; ks < 8; ks++) {
        int k0 = ks * 8;
        unsigned a0 = sX[(m0 + gid)     * XS + k0 + tig];
        unsigned a1 = sX[(m0 + gid + 8) * XS + k0 + tig];
        unsigned a2 = sX[(m0 + gid)     * XS + k0 + tig + 4];
        unsigned a3 = sX[(m0 + gid + 8) * XS + k0 + tig + 4];
#pragma unroll
        for (int nt = 0; nt < 8; nt++) {
            unsigned b0 = f2tf(__ldg(&W[(k0 + tig)     * 64 + nt * 8 + gid]));
            unsigned b1 = f2tf(__ldg(&W[(k0 + tig + 4) * 64 + nt * 8 + gid]));
            mma_tf32(d[nt], a0, a1, a2, a3, b0, b1);
        }
    }

    // epilogue: rows m0+gid (d0,d1) and m0+gid+8 (d2,d3), cols nt*8+2tig,+1
    int rowlo = base + m0 + gid;
    int rowhi = rowlo + 8;
    unsigned* Hu = (unsigned*)H;   // 32 uints (bf16x2) per 64-col row
#pragma unroll
    for (int nt = 0; nt < 8; nt++) {
        if (rowlo < N_NODES) {
            __nv_bfloat162 lo = __floats2bfloat162_rn(d[nt][0], d[nt][1]);
            Hu[(size_t)rowlo * 32 + nt * 4 + tig] = *reinterpret_cast<unsigned*>(&lo);
        }
        if (rowhi < N_NODES) {
            __nv_bfloat162 hi = __floats2bfloat162_rn(d[nt][2], d[nt][3]);
            Hu[(size_t)rowhi * 32 + nt * 4 + tig] = *reinterpret_cast<unsigned*>(&hi);
        }
    }

    // fused dots: each lane covers 16 cols of rows rowlo/rowhi; reduce over
    // the 4 lanes sharing gid (xor 1, 2 — lanes gid*4..gid*4+3 consecutive)
    float plo = 0.f, phi = 0.f, qlo = 0.f, qhi = 0.f;
#pragma unroll
    for (int nt = 0; nt < 8; nt++) {
        float2 as2 = ((const float2*)asrc)[nt * 4 + tig];
        float2 ad2 = ((const float2*)adst)[nt * 4 + tig];
        plo += d[nt][0] * as2.x + d[nt][1] * as2.y;
        phi += d[nt][2] * as2.x + d[nt][3] * as2.y;
        qlo += d[nt][0] * ad2.x + d[nt][1] * ad2.y;
        qhi += d[nt][2] * ad2.x + d[nt][3] * ad2.y;
    }
#pragma unroll
    for (int o = 1; o <= 2; o <<= 1) {
        plo += __shfl_xor_sync(FULLM, plo, o);
        phi += __shfl_xor_sync(FULLM, phi, o);
        qlo += __shfl_xor_sync(FULLM, qlo, o);
        qhi += __shfl_xor_sync(FULLM, qhi, o);
    }
    if (tig == 0) {
        if (rowlo < N_NODES) { g_ssrc[rowlo] = plo; g_sdst[rowlo] = qlo; }
        if (rowhi < N_NODES) { g_ssrc[rowhi] = phi; g_sdst[rowhi] = qhi; }
    }
}

// ---------------- fused softmax + aggregation: 4 nodes per warp -----------
template <bool DO_POOL>
__global__ __launch_bounds__(256) void k_attn(const __nv_bfloat16* __restrict__ H,
                                              const float* __restrict__ b,
                                              float* __restrict__ OUT) {
    __shared__ float sp[64];
    if (DO_POOL) {
        if (threadIdx.x < 64) sp[threadIdx.x] = 0.0f;
        __syncthreads();
    }

    int tid = threadIdx.x;
    int lane = tid & 31;
    int slane = lane & 7;
    int node = (blockIdx.x * 256 + tid) >> 3;

    int off = g_off[node];
    int deg = g_deg[node];
    float sd = g_sdst[node];

    int degmax = deg;
    degmax = max(degmax, __shfl_xor_sync(FULLM, degmax, 8));
    degmax = max(degmax, __shfl_xor_sync(FULLM, degmax, 16));

    const uint4* H4 = (const uint4*)H;

    float acc[8];
#pragma unroll
    for (int i = 0; i < 8; i++) acc[i] = 0.0f;
    float se = 0.0f;

    for (int jb = 0; jb < degmax; jb += 8) {
        int j = jb + slane;
        int s = 0; float ex = 0.0f;
        if (j < deg) {
            s = g_esrc[off + j];
            float e = g_ssrc[s] + sd;
            e = (e > 0.0f) ? e : NEG_SLOPE * e;
            ex = __expf(e);
        }
        se += ex;
#pragma unroll
        for (int k = 0; k < 8; k++) {
            float exk = __shfl_sync(FULLM, ex, k, 8);
            int   ss  = __shfl_sync(FULLM, s,  k, 8);
            if (exk > 0.0f) {
                uint4 v = H4[(size_t)ss * 8 + slane];
                acc[0] += exk * bflo(v.x);
                acc[1] += exk * bfhi(v.x);
                acc[2] += exk * bflo(v.y);
                acc[3] += exk * bfhi(v.y);
                acc[4] += exk * bflo(v.z);
                acc[5] += exk * bfhi(v.z);
                acc[6] += exk * bflo(v.w);
                acc[7] += exk * bfhi(v.w);
            }
        }
    }

    se += __shfl_xor_sync(FULLM, se, 1);
    se += __shfl_xor_sync(FULLM, se, 2);
    se += __shfl_xor_sync(FULLM, se, 4);
    float inv = 1.0f / (se + EPSV);

    float4 b0 = ((const float4*)b)[slane * 2];
    float4 b1 = ((const float4*)b)[slane * 2 + 1];
    float r[8];
    r[0] = fmaxf(acc[0] * inv + b0.x, 0.0f);
    r[1] = fmaxf(acc[1] * inv + b0.y, 0.0f);
    r[2] = fmaxf(acc[2] * inv + b0.z, 0.0f);
    r[3] = fmaxf(acc[3] * inv + b0.w, 0.0f);
    r[4] = fmaxf(acc[4] * inv + b1.x, 0.0f);
    r[5] = fmaxf(acc[5] * inv + b1.y, 0.0f);
    r[6] = fmaxf(acc[6] * inv + b1.z, 0.0f);
    r[7] = fmaxf(acc[7] * inv + b1.w, 0.0f);

    if (!DO_POOL) {
        ((float4*)OUT)[(size_t)node * 16 + slane * 2]     = make_float4(r[0], r[1], r[2], r[3]);
        ((float4*)OUT)[(size_t)node * 16 + slane * 2 + 1] = make_float4(r[4], r[5], r[6], r[7]);
    } else {
#pragma unroll
        for (int i = 0; i < 8; i++) {
            r[i] += __shfl_xor_sync(FULLM, r[i], 8);
            r[i] += __shfl_xor_sync(FULLM, r[i], 16);
        }
        if (lane < 8) {
#pragma unroll
            for (int i = 0; i < 8; i++)
                atomicAdd(&sp[slane * 8 + i], r[i]);
        }
        __syncthreads();
        if (tid < 64) atomicAdd(&g_pool[tid], sp[tid]);
    }
}

// ---------------- final: out = (pool/N) . W_out + b_out ----------------
__global__ void k_final(const float* __restrict__ Wout,
                        const float* __restrict__ bout,
                        float* __restrict__ out) {
    __shared__ float s[2];
    int t = threadIdx.x;      // 64 threads
    float v = (g_pool[t] * (1.0f / (float)N_NODES)) * Wout[t];
#pragma unroll
    for (int o = 16; o > 0; o >>= 1) v += __shfl_xor_sync(FULLM, v, o);
    if ((t & 31) == 0) s[t >> 5] = v;
    __syncthreads();
    if (t == 0) out[0] = s[0] + s[1] + bout[0];
}

// ---------------- launcher ----------------
extern "C" void kernel_launch(void* const* d_in, const int* in_sizes, int n_in,
                              void* d_out, int out_size) {
    const float* x      = (const float*)d_in[0];
    const int*   eidx   = (const int*)d_in[1];
    const float* W1     = (const float*)d_in[2];
    const float* a_src1 = (const float*)d_in[3];
    const float* a_dst1 = (const float*)d_in[4];
    const float* b1     = (const float*)d_in[5];
    const float* W2     = (const float*)d_in[6];
    const float* a_src2 = (const float*)d_in[7];
    const float* a_dst2 = (const float*)d_in[8];
    const float* b2     = (const float*)d_in[9];
    const float* W_out  = (const float*)d_in[10];
    const float* b_out  = (const float*)d_in[11];
    float* out = (float*)d_out;

    const int* src = eidx;
    const int* dst = eidx + N_EDGES;

    __nv_bfloat16* hA; cudaGetSymbolAddress((void**)&hA, g_hA);
    float* hB;   cudaGetSymbolAddress((void**)&hB, g_hB);
    int*   degp; cudaGetSymbolAddress((void**)&degp, g_deg);

    static cudaStream_t sB = nullptr;
    static cudaEvent_t evFork = nullptr, evJoin = nullptr;
    if (sB == nullptr) {
        cudaStreamCreateWithFlags(&sB, cudaStreamNonBlocking);
        cudaEventCreateWithFlags(&evFork, cudaEventDisableTiming);
        cudaEventCreateWithFlags(&evJoin, cudaEventDisableTiming);
    }

    int nbGemm = (N_NODES + TM - 1) / TM;   // 782
    int nbAttn = (N_NODES * 8) / 256;       // 3125 (exact)

    cudaEventRecord(evFork, 0);
    cudaStreamWaitEvent(sB, evFork, 0);

    // ---- CSR build on stream 0 ----
    cudaMemsetAsync(degp, 0, N_NODES * sizeof(int), 0);
    k_count<<<(N_EDGES + 255) / 256, 256>>>(dst);
    k_scanall<<<NB_SCAN, 1024>>>();
    k_fill<<<(N_TOT + 255) / 256, 256>>>(src, dst);

    // ---- gemm1 on sB, concurrent with the CSR chain ----
    k_gemm<<<nbGemm, 256, 0, sB>>>(x, W1, a_src1, a_dst1, hA);
    cudaEventRecord(evJoin, sB);
    cudaStreamWaitEvent(0, evJoin, 0);

    // layer 1 aggregate
    k_attn<false><<<nbAttn, 256>>>(hA, b1, hB);

    // layer 2
    k_gemm<<<nbGemm, 256>>>(hB, W2, a_src2, a_dst2, hA);
    k_attn<true><<<nbAttn, 256>>>(hA, b2, nullptr);

    k_final<<<1, 64>>>(W_out, b_out, out);
}